// round 1
// baseline (speedup 1.0000x reference)
#include <cuda_runtime.h>
#include <math.h>
#include <stdint.h>

#define HIDDEN 2048
#define SEQ    1024
#define BATCH  2
#define NHEADS 32
#define NGROUP 8
#define HDIM   64
#define MTOT   (BATCH * SEQ)      /* 2048 rows of (b,s) */
#define KVW    (NGROUP * HDIM)    /* 512 */

/* ---------------- scratch (no cudaMalloc allowed) ---------------- */
__device__ float g_q[MTOT * HIDDEN];     /* 16 MB */
__device__ float g_k[MTOT * KVW];        /*  4 MB */
__device__ float g_v[MTOT * KVW];        /*  4 MB */
__device__ float g_attn[MTOT * HIDDEN];  /* 16 MB */

/* =================================================================
 * NT SGEMM: C[m,n] = sum_k A[m,k] * B[n,k] + bias[n]
 * 128x128 tile, BK=8, 256 threads, 8x8 register micro-tile.
 * A, B both row-major with K contiguous (torch Linear layout).
 * M,N multiples of 128; K multiple of 8.
 * ================================================================= */
__global__ __launch_bounds__(256) void sgemm_nt(
    const float* __restrict__ A, const float* __restrict__ B,
    const float* __restrict__ bias, float* __restrict__ C,
    int M, int N, int K)
{
    __shared__ float As[8][128];
    __shared__ float Bs[8][128];

    const int tid = threadIdx.x;
    const int m0  = blockIdx.y * 128;
    const int n0  = blockIdx.x * 128;
    const int tx  = tid & 15;
    const int ty  = tid >> 4;

    /* loader: each thread brings one float4 of A and one of B per BK step */
    const int lrow = tid >> 1;           /* 0..127 */
    const int lcol = (tid & 1) * 4;      /* 0 or 4 */
    const float* Ag = A + (size_t)(m0 + lrow) * K + lcol;
    const float* Bg = B + (size_t)(n0 + lrow) * K + lcol;

    float acc[8][8];
#pragma unroll
    for (int i = 0; i < 8; i++)
#pragma unroll
        for (int j = 0; j < 8; j++) acc[i][j] = 0.0f;

    for (int k0 = 0; k0 < K; k0 += 8) {
        float4 av = *(const float4*)(Ag + k0);
        float4 bv = *(const float4*)(Bg + k0);
        __syncthreads();
        As[lcol + 0][lrow] = av.x;
        As[lcol + 1][lrow] = av.y;
        As[lcol + 2][lrow] = av.z;
        As[lcol + 3][lrow] = av.w;
        Bs[lcol + 0][lrow] = bv.x;
        Bs[lcol + 1][lrow] = bv.y;
        Bs[lcol + 2][lrow] = bv.z;
        Bs[lcol + 3][lrow] = bv.w;
        __syncthreads();

#pragma unroll
        for (int kk = 0; kk < 8; kk++) {
            float a[8], b[8];
            *(float4*)&a[0] = *(const float4*)&As[kk][ty * 8];
            *(float4*)&a[4] = *(const float4*)&As[kk][ty * 8 + 4];
            *(float4*)&b[0] = *(const float4*)&Bs[kk][tx * 8];
            *(float4*)&b[4] = *(const float4*)&Bs[kk][tx * 8 + 4];
#pragma unroll
            for (int i = 0; i < 8; i++)
#pragma unroll
                for (int j = 0; j < 8; j++)
                    acc[i][j] = fmaf(a[i], b[j], acc[i][j]);
        }
    }

    /* epilogue: add bias, vectorized store */
    float bb[8];
#pragma unroll
    for (int j = 0; j < 8; j++) bb[j] = bias[n0 + tx * 8 + j];

#pragma unroll
    for (int i = 0; i < 8; i++) {
        const size_t row = (size_t)(m0 + ty * 8 + i);
#pragma unroll
        for (int j = 0; j < 8; j += 4) {
            float4 r;
            r.x = acc[i][j + 0] + bb[j + 0];
            r.y = acc[i][j + 1] + bb[j + 1];
            r.z = acc[i][j + 2] + bb[j + 2];
            r.w = acc[i][j + 3] + bb[j + 3];
            *(float4*)&C[row * N + n0 + tx * 8 + j] = r;
        }
    }
}

/* =================================================================
 * Flash attention (causal, fp32).
 * Grid: (qtile=16, head=32, batch=2). 256 threads (16x16).
 * Tiles: 64 query rows x 64 key cols, d=64.
 * smem: Qs[64][65], Ks[64][65] (reused as P), Vs[64][64]  -> 49,664 B
 * Each thread owns a 4x4 block; row stats reduced over the 16
 * tx-lanes via shfl (they sit in contiguous warp halves).
 * ================================================================= */
#define QPAD 65
#define ATTN_SMEM_BYTES ((64 * QPAD * 2 + 64 * 64) * (int)sizeof(float))

__global__ __launch_bounds__(256) void attn_kernel(
    const float* __restrict__ Q, const float* __restrict__ Kp,
    const float* __restrict__ Vp, float* __restrict__ Out)
{
    extern __shared__ float sm[];
    float* Qs = sm;                   /* [64][65] */
    float* Ks = sm + 64 * QPAD;       /* [64][65], reused as P */
    float* Vs = sm + 2 * 64 * QPAD;   /* [64][64] */

    const int qt  = blockIdx.x;   /* 0..15  */
    const int h   = blockIdx.y;   /* 0..31  */
    const int b   = blockIdx.z;   /* 0..1   */
    const int g   = h >> 2;       /* KV group */
    const int tid = threadIdx.x;
    const int tx  = tid & 15;
    const int ty  = tid >> 4;
    const float scale = 0.125f;   /* 1/sqrt(64) */

    /* ---- load Q tile: rows b*SEQ + qt*64 + r, cols h*64 + d ---- */
    {
        const int r  = tid >> 2;
        const int c0 = (tid & 3) * 16;
        const float* src = Q + (size_t)(b * SEQ + qt * 64 + r) * HIDDEN + h * HDIM + c0;
#pragma unroll
        for (int u = 0; u < 4; u++) {
            float4 v = *(const float4*)(src + u * 4);
            float* dst = &Qs[r * QPAD + c0 + u * 4];
            dst[0] = v.x; dst[1] = v.y; dst[2] = v.z; dst[3] = v.w;
        }
    }

    float o[4][4];
    float mi[4], li[4];
#pragma unroll
    for (int i = 0; i < 4; i++) {
        mi[i] = -INFINITY;
        li[i] = 0.0f;
#pragma unroll
        for (int j = 0; j < 4; j++) o[i][j] = 0.0f;
    }

    for (int kt = 0; kt <= qt; kt++) {
        __syncthreads();  /* P (in Ks buf) fully consumed; Q store visible */

        /* ---- load K,V tiles for this kt ---- */
        {
            const int r  = tid >> 2;
            const int c0 = (tid & 3) * 16;
            const size_t rowbase = (size_t)(b * SEQ + kt * 64 + r) * KVW + g * HDIM + c0;
            const float* ks = Kp + rowbase;
            const float* vs = Vp + rowbase;
#pragma unroll
            for (int u = 0; u < 4; u++) {
                float4 kv = *(const float4*)(ks + u * 4);
                float* kd = &Ks[r * QPAD + c0 + u * 4];
                kd[0] = kv.x; kd[1] = kv.y; kd[2] = kv.z; kd[3] = kv.w;
                *(float4*)&Vs[r * 64 + c0 + u * 4] = *(const float4*)(vs + u * 4);
            }
        }
        __syncthreads();

        /* ---- S = Q @ K^T (4x4 per thread) ---- */
        float s[4][4];
#pragma unroll
        for (int i = 0; i < 4; i++)
#pragma unroll
            for (int j = 0; j < 4; j++) s[i][j] = 0.0f;

        for (int d = 0; d < 64; d++) {
            float a[4], bvv[4];
#pragma unroll
            for (int i = 0; i < 4; i++) a[i] = Qs[(ty * 4 + i) * QPAD + d];
#pragma unroll
            for (int j = 0; j < 4; j++) bvv[j] = Ks[(tx * 4 + j) * QPAD + d];
#pragma unroll
            for (int i = 0; i < 4; i++)
#pragma unroll
                for (int j = 0; j < 4; j++)
                    s[i][j] = fmaf(a[i], bvv[j], s[i][j]);
        }

        /* scale + causal mask (only diagonal tile needs masking) */
        if (kt == qt) {
#pragma unroll
            for (int i = 0; i < 4; i++)
#pragma unroll
                for (int j = 0; j < 4; j++)
                    s[i][j] = (tx * 4 + j > ty * 4 + i) ? -INFINITY : s[i][j] * scale;
        } else {
#pragma unroll
            for (int i = 0; i < 4; i++)
#pragma unroll
                for (int j = 0; j < 4; j++) s[i][j] *= scale;
        }

        /* ---- online softmax per row ---- */
#pragma unroll
        for (int i = 0; i < 4; i++) {
            float rmax = fmaxf(fmaxf(s[i][0], s[i][1]), fmaxf(s[i][2], s[i][3]));
#pragma unroll
            for (int off = 8; off >= 1; off >>= 1)
                rmax = fmaxf(rmax, __shfl_xor_sync(0xffffffffu, rmax, off));
            const float newm = fmaxf(mi[i], rmax);
            const float corr = __expf(mi[i] - newm);
            float rsum = 0.0f;
#pragma unroll
            for (int j = 0; j < 4; j++) {
                const float p = __expf(s[i][j] - newm);
                s[i][j] = p;
                rsum += p;
            }
#pragma unroll
            for (int off = 8; off >= 1; off >>= 1)
                rsum += __shfl_xor_sync(0xffffffffu, rsum, off);
            li[i] = li[i] * corr + rsum;
            mi[i] = newm;
#pragma unroll
            for (int j = 0; j < 4; j++) o[i][j] *= corr;
        }

        /* ---- write P into Ks buffer (aliased) ---- */
        __syncthreads();
#pragma unroll
        for (int i = 0; i < 4; i++)
#pragma unroll
            for (int j = 0; j < 4; j++)
                Ks[(ty * 4 + i) * QPAD + tx * 4 + j] = s[i][j];
        __syncthreads();

        /* ---- O += P @ V ---- */
        for (int j = 0; j < 64; j++) {
            float a[4];
#pragma unroll
            for (int i = 0; i < 4; i++) a[i] = Ks[(ty * 4 + i) * QPAD + j];
            const float4 bv = *(const float4*)&Vs[j * 64 + tx * 4];
#pragma unroll
            for (int i = 0; i < 4; i++) {
                o[i][0] = fmaf(a[i], bv.x, o[i][0]);
                o[i][1] = fmaf(a[i], bv.y, o[i][1]);
                o[i][2] = fmaf(a[i], bv.z, o[i][2]);
                o[i][3] = fmaf(a[i], bv.w, o[i][3]);
            }
        }
    }

    /* ---- finalize: O /= l, write [b,s,h,d] packed as [M, HIDDEN] ---- */
#pragma unroll
    for (int i = 0; i < 4; i++) {
        const float inv = 1.0f / li[i];
        float4 w;
        w.x = o[i][0] * inv;
        w.y = o[i][1] * inv;
        w.z = o[i][2] * inv;
        w.w = o[i][3] * inv;
        const size_t row = (size_t)(b * SEQ + qt * 64 + ty * 4 + i);
        *(float4*)&Out[row * HIDDEN + h * HDIM + tx * 4] = w;
    }
}

/* ================================================================= */
extern "C" void kernel_launch(void* const* d_in, const int* in_sizes, int n_in,
                              void* d_out, int out_size)
{
    (void)in_sizes; (void)n_in; (void)out_size;
    const float* x  = (const float*)d_in[0];
    /* d_in[1] is the causal mask: implemented analytically, not read */
    const float* Wq = (const float*)d_in[2];
    const float* bq = (const float*)d_in[3];
    const float* Wk = (const float*)d_in[4];
    const float* bk = (const float*)d_in[5];
    const float* Wv = (const float*)d_in[6];
    const float* bv = (const float*)d_in[7];
    const float* Wo = (const float*)d_in[8];
    const float* bo = (const float*)d_in[9];
    float* out = (float*)d_out;

    float *q, *k, *v, *attn;
    cudaGetSymbolAddress((void**)&q,    g_q);
    cudaGetSymbolAddress((void**)&k,    g_k);
    cudaGetSymbolAddress((void**)&v,    g_v);
    cudaGetSymbolAddress((void**)&attn, g_attn);

    cudaFuncSetAttribute(attn_kernel,
                         cudaFuncAttributeMaxDynamicSharedMemorySize,
                         ATTN_SMEM_BYTES);

    /* projections */
    sgemm_nt<<<dim3(HIDDEN / 128, MTOT / 128), 256>>>(x, Wq, bq, q, MTOT, HIDDEN, HIDDEN);
    sgemm_nt<<<dim3(KVW    / 128, MTOT / 128), 256>>>(x, Wk, bk, k, MTOT, KVW,    HIDDEN);
    sgemm_nt<<<dim3(KVW    / 128, MTOT / 128), 256>>>(x, Wv, bv, v, MTOT, KVW,    HIDDEN);

    /* causal GQA attention */
    attn_kernel<<<dim3(SEQ / 64, NHEADS, BATCH), 256, ATTN_SMEM_BYTES>>>(q, k, v, attn);

    /* output projection */
    sgemm_nt<<<dim3(HIDDEN / 128, MTOT / 128), 256>>>(attn, Wo, bo, out, MTOT, HIDDEN, HIDDEN);
}

// round 2
// speedup vs baseline: 2.8670x; 2.8670x over previous
#include <cuda_runtime.h>
#include <math.h>
#include <stdint.h>

#define HIDDEN 2048
#define SEQ    1024
#define BATCH  2
#define NHEADS 32
#define NGROUP 8
#define HDIM   64
#define MTOT   (BATCH * SEQ)
#define KVW    (NGROUP * HDIM)   /* 512 */

/* ---------------- scratch (no cudaMalloc allowed) ---------------- */
__device__ float g_q[MTOT * HIDDEN];
__device__ float g_k[MTOT * KVW];
__device__ float g_v[MTOT * KVW];
__device__ float g_attn[MTOT * HIDDEN];

/* ---------------- tf32 helpers ---------------- */
__device__ __forceinline__ uint32_t f2tf32(float x) {
    uint32_t r;
    asm("cvt.rna.tf32.f32 %0, %1;" : "=r"(r) : "f"(x));
    return r;
}

__device__ __forceinline__ void mma_tf32(float* c, const uint32_t* a,
                                         uint32_t b0, uint32_t b1) {
    asm volatile(
        "mma.sync.aligned.m16n8k8.row.col.f32.tf32.tf32.f32 "
        "{%0,%1,%2,%3}, {%4,%5,%6,%7}, {%8,%9}, {%0,%1,%2,%3};"
        : "+f"(c[0]), "+f"(c[1]), "+f"(c[2]), "+f"(c[3])
        : "r"(a[0]), "r"(a[1]), "r"(a[2]), "r"(a[3]), "r"(b0), "r"(b1));
}

__device__ __forceinline__ void cvt_store4(uint32_t* dst, float4 v) {
    uint4 u;
    u.x = f2tf32(v.x); u.y = f2tf32(v.y);
    u.z = f2tf32(v.z); u.w = f2tf32(v.w);
    *(uint4*)dst = u;
}

/* =================================================================
 * TF32 NT GEMM core: C[m,n] = sum_k A[m,k]*B[n,k] + bias[n]
 * 128x128 tile, BK=16, 256 threads (8 warps: 4m x 2n), warp 32x64.
 * Double-buffered smem, fragments via direct LDS (stride 20 ->
 * conflict-free fragment reads).
 * ================================================================= */
#define GS 20

__device__ __forceinline__ void gemm_core(
    const float* __restrict__ A, const float* __restrict__ B,
    const float* __restrict__ bias, float* __restrict__ C,
    int ldc, int K, int m0, int n0)
{
    __shared__ uint32_t As[2][128 * GS];
    __shared__ uint32_t Bs[2][128 * GS];

    const int tid = threadIdx.x, lane = tid & 31, wid = tid >> 5;
    const int wm = (wid & 3) * 32, wn = (wid >> 2) * 64;
    const int r0 = lane >> 2, a4 = lane & 3;

    float acc[2][8][4];
#pragma unroll
    for (int mt = 0; mt < 2; mt++)
#pragma unroll
        for (int nt = 0; nt < 8; nt++) {
            acc[mt][nt][0] = 0.f; acc[mt][nt][1] = 0.f;
            acc[mt][nt][2] = 0.f; acc[mt][nt][3] = 0.f;
        }

    const int lr = tid >> 1, lc = (tid & 1) * 8;
    const float* Ag = A + (size_t)(m0 + lr) * K + lc;
    const float* Bg = B + (size_t)(n0 + lr) * K + lc;
    const int so = lr * GS + lc;

    /* prologue: tile 0 */
    {
        float4 a0 = *(const float4*)Ag, a1 = *(const float4*)(Ag + 4);
        float4 b0 = *(const float4*)Bg, b1 = *(const float4*)(Bg + 4);
        cvt_store4(&As[0][so], a0); cvt_store4(&As[0][so + 4], a1);
        cvt_store4(&Bs[0][so], b0); cvt_store4(&Bs[0][so + 4], b1);
    }
    __syncthreads();

    const int nIter = K >> 4;
    for (int it = 0; it < nIter; it++) {
        const int cur = it & 1;
        float4 pa0, pa1, pb0, pb1;
        if (it + 1 < nIter) {
            const float* Ap = Ag + (it + 1) * 16;
            const float* Bp = Bg + (it + 1) * 16;
            pa0 = *(const float4*)Ap; pa1 = *(const float4*)(Ap + 4);
            pb0 = *(const float4*)Bp; pb1 = *(const float4*)(Bp + 4);
        }
        const uint32_t* Ab = As[cur];
        const uint32_t* Bb = Bs[cur];
#pragma unroll
        for (int ks = 0; ks < 2; ks++) {
            uint32_t af[2][4];
            const int c = ks * 8 + a4;
#pragma unroll
            for (int mt = 0; mt < 2; mt++) {
                const int r = wm + mt * 16 + r0;
                af[mt][0] = Ab[r * GS + c];
                af[mt][1] = Ab[(r + 8) * GS + c];
                af[mt][2] = Ab[r * GS + c + 4];
                af[mt][3] = Ab[(r + 8) * GS + c + 4];
            }
#pragma unroll
            for (int nt = 0; nt < 8; nt++) {
                const int n = wn + nt * 8 + r0;
                uint32_t b0 = Bb[n * GS + c];
                uint32_t b1 = Bb[n * GS + c + 4];
                mma_tf32(acc[0][nt], af[0], b0, b1);
                mma_tf32(acc[1][nt], af[1], b0, b1);
            }
        }
        if (it + 1 < nIter) {
            const int nxt = 1 - cur;
            cvt_store4(&As[nxt][so], pa0); cvt_store4(&As[nxt][so + 4], pa1);
            cvt_store4(&Bs[nxt][so], pb0); cvt_store4(&Bs[nxt][so + 4], pb1);
        }
        __syncthreads();
    }

    /* epilogue: bias + float2 stores */
#pragma unroll
    for (int mt = 0; mt < 2; mt++) {
#pragma unroll
        for (int nt = 0; nt < 8; nt++) {
            const int col = n0 + wn + nt * 8 + 2 * a4;
            const float b0 = bias[col], b1 = bias[col + 1];
            const int rA = m0 + wm + mt * 16 + r0;
            float2 v0 = make_float2(acc[mt][nt][0] + b0, acc[mt][nt][1] + b1);
            float2 v1 = make_float2(acc[mt][nt][2] + b0, acc[mt][nt][3] + b1);
            *(float2*)&C[(size_t)rA * ldc + col] = v0;
            *(float2*)&C[(size_t)(rA + 8) * ldc + col] = v1;
        }
    }
}

/* fused QKV projection: grid (24, 16) */
__global__ __launch_bounds__(256) void qkv_gemm(
    const float* __restrict__ x,
    const float* __restrict__ Wq, const float* __restrict__ bq,
    const float* __restrict__ Wk, const float* __restrict__ bk,
    const float* __restrict__ Wv, const float* __restrict__ bv)
{
    const int bx = blockIdx.x;
    const float* B; const float* bias; float* C; int ldc; int n0;
    if (bx < 16)      { B = Wq; bias = bq; C = g_q; ldc = HIDDEN; n0 = bx * 128; }
    else if (bx < 20) { B = Wk; bias = bk; C = g_k; ldc = KVW;    n0 = (bx - 16) * 128; }
    else              { B = Wv; bias = bv; C = g_v; ldc = KVW;    n0 = (bx - 20) * 128; }
    gemm_core(x, B, bias, C, ldc, HIDDEN, blockIdx.y * 128, n0);
}

/* generic GEMM (O-projection): grid (N/128, M/128) */
__global__ __launch_bounds__(256) void gemm_tf32(
    const float* __restrict__ A, const float* __restrict__ B,
    const float* __restrict__ bias, float* __restrict__ C,
    int ldc, int K)
{
    gemm_core(A, B, bias, C, ldc, K, blockIdx.y * 128, blockIdx.x * 128);
}

/* =================================================================
 * Tensor-core flash attention (causal, GQA).
 * Block: 128 threads (4 warps), each warp owns 16 query rows.
 * Q fragments hoisted to registers (pre-scaled, tf32).
 * smem: Ks[64][68] (aliased with P), Vt[64][68] (V transposed).
 * Stride 68 -> conflict-free mma fragment LDS.
 * ================================================================= */
#define ATS 68

__global__ __launch_bounds__(128) void attn_tc(
    const float* __restrict__ Q, const float* __restrict__ Kp,
    const float* __restrict__ Vp, float* __restrict__ Out)
{
    __shared__ uint32_t Ks[64 * ATS];   /* aliased with P after S-compute */
    __shared__ uint32_t Vt[64 * ATS];

    const int qt = blockIdx.x, h = blockIdx.y, b = blockIdx.z, g = h >> 2;
    const int tid = threadIdx.x, lane = tid & 31, w = tid >> 5;
    const int r0 = lane >> 2, a4 = lane & 3;

    /* ---- hoist Q fragments (scaled by 1/sqrt(d), tf32) ---- */
    uint32_t qf[8][4];
    {
        const float sc = 0.125f;
        const float* qp = Q + (size_t)(b * SEQ + qt * 64 + w * 16) * HIDDEN + h * HDIM;
#pragma unroll
        for (int ks = 0; ks < 8; ks++) {
            const int c = ks * 8 + a4;
            qf[ks][0] = f2tf32(qp[(size_t)r0 * HIDDEN + c] * sc);
            qf[ks][1] = f2tf32(qp[(size_t)(r0 + 8) * HIDDEN + c] * sc);
            qf[ks][2] = f2tf32(qp[(size_t)r0 * HIDDEN + c + 4] * sc);
            qf[ks][3] = f2tf32(qp[(size_t)(r0 + 8) * HIDDEN + c + 4] * sc);
        }
    }

    float o[8][4];
#pragma unroll
    for (int nt = 0; nt < 8; nt++) {
        o[nt][0] = 0.f; o[nt][1] = 0.f; o[nt][2] = 0.f; o[nt][3] = 0.f;
    }
    float mi0 = -1e30f, mi1 = -1e30f, l0 = 0.f, l1 = 0.f;

    const int lrow = tid >> 1;          /* 0..63 */
    const int lcb  = (tid & 1) * 32;    /* 0 / 32 */

    for (int kt = 0; kt <= qt; kt++) {
        __syncthreads();   /* previous P/V consumers done */

        /* ---- load K tile (row-major) + V tile (transposed) ---- */
        {
            const size_t base = (size_t)(b * SEQ + kt * 64 + lrow) * KVW + g * HDIM + lcb;
            const float* kp = Kp + base;
            const float* vp = Vp + base;
#pragma unroll
            for (int u = 0; u < 8; u++) {
                float4 kv = *(const float4*)(kp + u * 4);
                cvt_store4(&Ks[lrow * ATS + lcb + u * 4], kv);
                float4 vv = *(const float4*)(vp + u * 4);
                const int c = lcb + u * 4;
                Vt[(c + 0) * ATS + lrow] = f2tf32(vv.x);
                Vt[(c + 1) * ATS + lrow] = f2tf32(vv.y);
                Vt[(c + 2) * ATS + lrow] = f2tf32(vv.z);
                Vt[(c + 3) * ATS + lrow] = f2tf32(vv.w);
            }
        }
        __syncthreads();

        /* ---- S = Q K^T ---- */
        float s[8][4];
#pragma unroll
        for (int nt = 0; nt < 8; nt++) {
            s[nt][0] = 0.f; s[nt][1] = 0.f; s[nt][2] = 0.f; s[nt][3] = 0.f;
        }
#pragma unroll
        for (int ks = 0; ks < 8; ks++) {
            const int c = ks * 8 + a4;
#pragma unroll
            for (int nt = 0; nt < 8; nt++) {
                const int n = nt * 8 + r0;
                uint32_t b0 = Ks[n * ATS + c];
                uint32_t b1 = Ks[n * ATS + c + 4];
                mma_tf32(s[nt], qf[ks], b0, b1);
            }
        }

        /* ---- causal mask (diagonal tile only) ---- */
        if (kt == qt) {
            const int row0 = w * 16 + r0, row1 = row0 + 8;
#pragma unroll
            for (int nt = 0; nt < 8; nt++) {
                const int c0 = nt * 8 + 2 * a4, c1 = c0 + 1;
                if (c0 > row0) s[nt][0] = -1e30f;
                if (c1 > row0) s[nt][1] = -1e30f;
                if (c0 > row1) s[nt][2] = -1e30f;
                if (c1 > row1) s[nt][3] = -1e30f;
            }
        }

        /* ---- online softmax (rows r0, r0+8; quad shfl reduce) ---- */
        float mx0 = -1e30f, mx1 = -1e30f;
#pragma unroll
        for (int nt = 0; nt < 8; nt++) {
            mx0 = fmaxf(mx0, fmaxf(s[nt][0], s[nt][1]));
            mx1 = fmaxf(mx1, fmaxf(s[nt][2], s[nt][3]));
        }
        mx0 = fmaxf(mx0, __shfl_xor_sync(0xffffffffu, mx0, 1));
        mx0 = fmaxf(mx0, __shfl_xor_sync(0xffffffffu, mx0, 2));
        mx1 = fmaxf(mx1, __shfl_xor_sync(0xffffffffu, mx1, 1));
        mx1 = fmaxf(mx1, __shfl_xor_sync(0xffffffffu, mx1, 2));
        const float nm0 = fmaxf(mi0, mx0), nm1 = fmaxf(mi1, mx1);
        const float cr0 = __expf(mi0 - nm0), cr1 = __expf(mi1 - nm1);
        float sum0 = 0.f, sum1 = 0.f;
#pragma unroll
        for (int nt = 0; nt < 8; nt++) {
            s[nt][0] = __expf(s[nt][0] - nm0);
            s[nt][1] = __expf(s[nt][1] - nm0);
            s[nt][2] = __expf(s[nt][2] - nm1);
            s[nt][3] = __expf(s[nt][3] - nm1);
            sum0 += s[nt][0] + s[nt][1];
            sum1 += s[nt][2] + s[nt][3];
        }
        sum0 += __shfl_xor_sync(0xffffffffu, sum0, 1);
        sum0 += __shfl_xor_sync(0xffffffffu, sum0, 2);
        sum1 += __shfl_xor_sync(0xffffffffu, sum1, 1);
        sum1 += __shfl_xor_sync(0xffffffffu, sum1, 2);
        l0 = l0 * cr0 + sum0;  l1 = l1 * cr1 + sum1;
        mi0 = nm0;             mi1 = nm1;
#pragma unroll
        for (int nt = 0; nt < 8; nt++) {
            o[nt][0] *= cr0; o[nt][1] *= cr0;
            o[nt][2] *= cr1; o[nt][3] *= cr1;
        }

        __syncthreads();   /* all warps finished reading Ks */

        /* ---- store P (tf32) into Ks alias ---- */
        {
            const int row0 = w * 16 + r0;
#pragma unroll
            for (int nt = 0; nt < 8; nt++) {
                const int c = nt * 8 + 2 * a4;
                Ks[row0 * ATS + c]           = f2tf32(s[nt][0]);
                Ks[row0 * ATS + c + 1]       = f2tf32(s[nt][1]);
                Ks[(row0 + 8) * ATS + c]     = f2tf32(s[nt][2]);
                Ks[(row0 + 8) * ATS + c + 1] = f2tf32(s[nt][3]);
            }
        }
        __syncthreads();

        /* ---- O += P @ V ---- */
#pragma unroll
        for (int ks = 0; ks < 8; ks++) {
            const int row0 = w * 16 + r0;
            uint32_t pa[4];
            pa[0] = Ks[row0 * ATS + ks * 8 + a4];
            pa[1] = Ks[(row0 + 8) * ATS + ks * 8 + a4];
            pa[2] = Ks[row0 * ATS + ks * 8 + a4 + 4];
            pa[3] = Ks[(row0 + 8) * ATS + ks * 8 + a4 + 4];
#pragma unroll
            for (int nt = 0; nt < 8; nt++) {
                uint32_t b0 = Vt[(nt * 8 + r0) * ATS + ks * 8 + a4];
                uint32_t b1 = Vt[(nt * 8 + r0) * ATS + ks * 8 + a4 + 4];
                mma_tf32(o[nt], pa, b0, b1);
            }
        }
    }

    /* ---- finalize ---- */
    const float inv0 = 1.f / l0, inv1 = 1.f / l1;
    const size_t row0 = (size_t)(b * SEQ + qt * 64 + w * 16 + r0);
#pragma unroll
    for (int nt = 0; nt < 8; nt++) {
        const int col = h * HDIM + nt * 8 + 2 * a4;
        *(float2*)&Out[row0 * HIDDEN + col] =
            make_float2(o[nt][0] * inv0, o[nt][1] * inv0);
        *(float2*)&Out[(row0 + 8) * HIDDEN + col] =
            make_float2(o[nt][2] * inv1, o[nt][3] * inv1);
    }
}

/* ================================================================= */
extern "C" void kernel_launch(void* const* d_in, const int* in_sizes, int n_in,
                              void* d_out, int out_size)
{
    (void)in_sizes; (void)n_in; (void)out_size;
    const float* x  = (const float*)d_in[0];
    /* d_in[1] = causal mask, handled analytically */
    const float* Wq = (const float*)d_in[2];
    const float* bq = (const float*)d_in[3];
    const float* Wk = (const float*)d_in[4];
    const float* bk = (const float*)d_in[5];
    const float* Wv = (const float*)d_in[6];
    const float* bv = (const float*)d_in[7];
    const float* Wo = (const float*)d_in[8];
    const float* bo = (const float*)d_in[9];
    float* out = (float*)d_out;

    float *q, *k, *v, *attn;
    cudaGetSymbolAddress((void**)&q,    g_q);
    cudaGetSymbolAddress((void**)&k,    g_k);
    cudaGetSymbolAddress((void**)&v,    g_v);
    cudaGetSymbolAddress((void**)&attn, g_attn);

    /* fused Q/K/V projection */
    qkv_gemm<<<dim3(24, 16), 256>>>(x, Wq, bq, Wk, bk, Wv, bv);

    /* causal GQA attention (tensor cores) */
    attn_tc<<<dim3(SEQ / 64, NHEADS, BATCH), 128>>>(q, k, v, attn);

    /* output projection */
    gemm_tf32<<<dim3(HIDDEN / 128, MTOT / 128), 256>>>(attn, Wo, bo, out,
                                                       HIDDEN, HIDDEN);
}

// round 4
// speedup vs baseline: 3.1509x; 1.0990x over previous
#include <cuda_runtime.h>
#include <math.h>
#include <stdint.h>

#define HIDDEN 2048
#define SEQ    1024
#define BATCH  2
#define NHEADS 32
#define NGROUP 8
#define HDIM   64
#define MTOT   (BATCH * SEQ)
#define KVW    (NGROUP * HDIM)   /* 512 */

/* ---------------- scratch (no cudaMalloc allowed) ---------------- */
__device__ float g_q[MTOT * HIDDEN];
__device__ float g_k[MTOT * KVW];
__device__ float g_v[MTOT * KVW];
__device__ float g_attn[MTOT * HIDDEN];

/* ---------------- helpers ---------------- */
__device__ __forceinline__ uint32_t f2tf32(float x) {
    uint32_t r;
    asm("cvt.rna.tf32.f32 %0, %1;" : "=r"(r) : "f"(x));
    return r;
}
__device__ __forceinline__ uint32_t smem_u32(const void* p) {
    uint32_t a;
    asm("{ .reg .u64 t; cvta.to.shared.u64 t, %1; cvt.u32.u64 %0, t; }"
        : "=r"(a) : "l"(p));
    return a;
}
__device__ __forceinline__ void mma_tf32(float* c, const uint32_t* a,
                                         uint32_t b0, uint32_t b1) {
    asm volatile(
        "mma.sync.aligned.m16n8k8.row.col.f32.tf32.tf32.f32 "
        "{%0,%1,%2,%3}, {%4,%5,%6,%7}, {%8,%9}, {%0,%1,%2,%3};"
        : "+f"(c[0]), "+f"(c[1]), "+f"(c[2]), "+f"(c[3])
        : "r"(a[0]), "r"(a[1]), "r"(a[2]), "r"(a[3]), "r"(b0), "r"(b1));
}
/* tf32 fragment via ldmatrix (b16 view): 4 regs from 4 lane-group addrs */
__device__ __forceinline__ void ldsm_x4(uint32_t* r, uint32_t addr) {
    asm volatile("ldmatrix.sync.aligned.m8n8.x4.shared.b16 {%0,%1,%2,%3}, [%4];"
        : "=r"(r[0]), "=r"(r[1]), "=r"(r[2]), "=r"(r[3]) : "r"(addr));
}
__device__ __forceinline__ void cvt_store4(uint32_t* dst, float4 v) {
    uint4 u;
    u.x = f2tf32(v.x); u.y = f2tf32(v.y);
    u.z = f2tf32(v.z); u.w = f2tf32(v.w);
    *(uint4*)dst = u;
}

/* =================================================================
 * TF32 NT GEMM: C[m,n] = sum_k A[m,k]*B[n,k] + bias[n]
 * 128x128 tile, BK=16, 256 threads (8 warps: 4m x 2n), warp 32x64.
 * Double-buffered smem (stride 20 floats = 80B -> conflict-free
 * LDSM row groups). Fragments via ldmatrix.x4.
 * ================================================================= */
#define GS 20

__device__ __forceinline__ void gemm_core(
    const float* __restrict__ A, const float* __restrict__ B,
    const float* __restrict__ bias, float* __restrict__ C,
    int ldc, int K, int m0, int n0)
{
    __shared__ uint32_t As[2][128 * GS];
    __shared__ uint32_t Bs[2][128 * GS];

    const int tid = threadIdx.x, lane = tid & 31, wid = tid >> 5;
    const int wm = (wid & 3) * 32, wn = (wid >> 2) * 64;

    /* ldmatrix lane-group addressing:
       A frag (mt,ks): groups = rows+0 | rows+8 | +16B | rows+8,+16B */
    const int grp = lane >> 3;
    const uint32_t aOff = (uint32_t)(wm + (lane & 7) + ((grp & 1) << 3)) * 80
                        + (uint32_t)(grp >> 1) * 16;
    const uint32_t bOff = (uint32_t)(wn + (lane & 7) + ((grp >> 1) << 3)) * 80
                        + (uint32_t)(grp & 1) * 16;

    float acc[2][8][4];
#pragma unroll
    for (int mt = 0; mt < 2; mt++)
#pragma unroll
        for (int nt = 0; nt < 8; nt++) {
            acc[mt][nt][0] = 0.f; acc[mt][nt][1] = 0.f;
            acc[mt][nt][2] = 0.f; acc[mt][nt][3] = 0.f;
        }

    const int lr = tid >> 1, lc = (tid & 1) * 8;
    const float* Ag = A + (size_t)(m0 + lr) * K + lc;
    const float* Bg = B + (size_t)(n0 + lr) * K + lc;
    const int so = lr * GS + lc;

    /* prologue: tile 0 */
    {
        float4 a0 = *(const float4*)Ag, a1 = *(const float4*)(Ag + 4);
        float4 b0 = *(const float4*)Bg, b1 = *(const float4*)(Bg + 4);
        cvt_store4(&As[0][so], a0); cvt_store4(&As[0][so + 4], a1);
        cvt_store4(&Bs[0][so], b0); cvt_store4(&Bs[0][so + 4], b1);
    }
    __syncthreads();

    const int nIter = K >> 4;
    for (int it = 0; it < nIter; it++) {
        const int cur = it & 1;
        float4 pa0, pa1, pb0, pb1;
        if (it + 1 < nIter) {
            const float* Ap = Ag + (it + 1) * 16;
            const float* Bp = Bg + (it + 1) * 16;
            pa0 = *(const float4*)Ap; pa1 = *(const float4*)(Ap + 4);
            pb0 = *(const float4*)Bp; pb1 = *(const float4*)(Bp + 4);
        }
        const uint32_t aBase = smem_u32(&As[cur][0]);
        const uint32_t bBase = smem_u32(&Bs[cur][0]);
#pragma unroll
        for (int ks = 0; ks < 2; ks++) {
            uint32_t af[2][4];
            ldsm_x4(af[0], aBase + aOff + ks * 32);          /* mt=0 */
            ldsm_x4(af[1], aBase + aOff + 1280 + ks * 32);   /* mt=1 (+16 rows) */
#pragma unroll
            for (int nt2 = 0; nt2 < 4; nt2++) {
                uint32_t bf[4];
                ldsm_x4(bf, bBase + bOff + nt2 * 1280 + ks * 32);
                mma_tf32(acc[0][2 * nt2],     af[0], bf[0], bf[1]);
                mma_tf32(acc[0][2 * nt2 + 1], af[0], bf[2], bf[3]);
                mma_tf32(acc[1][2 * nt2],     af[1], bf[0], bf[1]);
                mma_tf32(acc[1][2 * nt2 + 1], af[1], bf[2], bf[3]);
            }
        }
        if (it + 1 < nIter) {
            const int nxt = 1 - cur;
            cvt_store4(&As[nxt][so], pa0); cvt_store4(&As[nxt][so + 4], pa1);
            cvt_store4(&Bs[nxt][so], pb0); cvt_store4(&Bs[nxt][so + 4], pb1);
        }
        __syncthreads();
    }

    /* epilogue: bias + float2 stores */
    const int r0 = lane >> 2, a4 = lane & 3;
#pragma unroll
    for (int mt = 0; mt < 2; mt++) {
#pragma unroll
        for (int nt = 0; nt < 8; nt++) {
            const int col = n0 + wn + nt * 8 + 2 * a4;
            const float b0 = bias[col], b1 = bias[col + 1];
            const int rA = m0 + wm + mt * 16 + r0;
            float2 v0 = make_float2(acc[mt][nt][0] + b0, acc[mt][nt][1] + b1);
            float2 v1 = make_float2(acc[mt][nt][2] + b0, acc[mt][nt][3] + b1);
            *(float2*)&C[(size_t)rA * ldc + col] = v0;
            *(float2*)&C[(size_t)(rA + 8) * ldc + col] = v1;
        }
    }
}

/* fused QKV projection: grid (24, 16) */
__global__ __launch_bounds__(256) void qkv_gemm(
    const float* __restrict__ x,
    const float* __restrict__ Wq, const float* __restrict__ bq,
    const float* __restrict__ Wk, const float* __restrict__ bk,
    const float* __restrict__ Wv, const float* __restrict__ bv)
{
    const int bx = blockIdx.x;
    const float* B; const float* bias; float* C; int ldc; int n0;
    if (bx < 16)      { B = Wq; bias = bq; C = g_q; ldc = HIDDEN; n0 = bx * 128; }
    else if (bx < 20) { B = Wk; bias = bk; C = g_k; ldc = KVW;    n0 = (bx - 16) * 128; }
    else              { B = Wv; bias = bv; C = g_v; ldc = KVW;    n0 = (bx - 20) * 128; }
    gemm_core(x, B, bias, C, ldc, HIDDEN, blockIdx.y * 128, n0);
}

/* generic GEMM (O-projection): grid (N/128, M/128) */
__global__ __launch_bounds__(256) void gemm_tf32(
    const float* __restrict__ A, const float* __restrict__ B,
    const float* __restrict__ bias, float* __restrict__ C,
    int ldc, int K)
{
    gemm_core(A, B, bias, C, ldc, K, blockIdx.y * 128, blockIdx.x * 128);
}

/* =================================================================
 * Tensor-core flash attention (causal, GQA), mma.sync tf32 +
 * ldmatrix fragments. Block 128 threads (4 warps x 16 query rows).
 * smem: Ks[64][68] (aliased with P), Vt[64][68] transposed.
 * 272B row stride -> conflict-free LDSM (row*17 mod 8 distinct).
 * ================================================================= */
#define ATS 68

__global__ __launch_bounds__(128) void attn_tc(
    const float* __restrict__ Q, const float* __restrict__ Kp,
    const float* __restrict__ Vp, float* __restrict__ Out)
{
    __shared__ uint32_t Ks[64 * ATS];   /* aliased with P after S-compute */
    __shared__ uint32_t Vt[64 * ATS];

    const int qt = blockIdx.x, h = blockIdx.y, b = blockIdx.z, g = h >> 2;
    const int tid = threadIdx.x, lane = tid & 31, w = tid >> 5;
    const int r0 = lane >> 2, a4 = lane & 3;

    /* ldmatrix lane-group offsets (bytes) */
    const int grp = lane >> 3;
    const uint32_t paOff = (uint32_t)(w * 16 + (lane & 7) + ((grp & 1) << 3)) * 272
                         + (uint32_t)(grp >> 1) * 16;      /* P A-fragment */
    const uint32_t bfOff = (uint32_t)((lane & 7) + ((grp >> 1) << 3)) * 272
                         + (uint32_t)(grp & 1) * 16;       /* K/V B-fragment */
    const uint32_t ksBase = smem_u32(Ks);
    const uint32_t vtBase = smem_u32(Vt);

    /* ---- hoist Q fragments (scaled, tf32) ---- */
    uint32_t qf[8][4];
    {
        const float sc = 0.125f;
        const float* qp = Q + (size_t)(b * SEQ + qt * 64 + w * 16) * HIDDEN + h * HDIM;
#pragma unroll
        for (int ks = 0; ks < 8; ks++) {
            const int c = ks * 8 + a4;
            qf[ks][0] = f2tf32(qp[(size_t)r0 * HIDDEN + c] * sc);
            qf[ks][1] = f2tf32(qp[(size_t)(r0 + 8) * HIDDEN + c] * sc);
            qf[ks][2] = f2tf32(qp[(size_t)r0 * HIDDEN + c + 4] * sc);
            qf[ks][3] = f2tf32(qp[(size_t)(r0 + 8) * HIDDEN + c + 4] * sc);
        }
    }

    float o[8][4];
#pragma unroll
    for (int nt = 0; nt < 8; nt++) {
        o[nt][0] = 0.f; o[nt][1] = 0.f; o[nt][2] = 0.f; o[nt][3] = 0.f;
    }
    float mi0 = -1e30f, mi1 = -1e30f, l0 = 0.f, l1 = 0.f;

    const int lrow = tid >> 1;
    const int lcb  = (tid & 1) * 32;

    for (int kt = 0; kt <= qt; kt++) {
        __syncthreads();
        /* ---- stage K (row-major) + V (transposed) ---- */
        {
            const size_t base = (size_t)(b * SEQ + kt * 64 + lrow) * KVW + g * HDIM + lcb;
            const float* kp = Kp + base;
            const float* vp = Vp + base;
#pragma unroll
            for (int u = 0; u < 8; u++) {
                float4 kv = *(const float4*)(kp + u * 4);
                cvt_store4(&Ks[lrow * ATS + lcb + u * 4], kv);
                float4 vv = *(const float4*)(vp + u * 4);
                const int c = lcb + u * 4;
                Vt[(c + 0) * ATS + lrow] = f2tf32(vv.x);
                Vt[(c + 1) * ATS + lrow] = f2tf32(vv.y);
                Vt[(c + 2) * ATS + lrow] = f2tf32(vv.z);
                Vt[(c + 3) * ATS + lrow] = f2tf32(vv.w);
            }
        }
        __syncthreads();

        /* ---- S = Q K^T (ldmatrix B-fragments) ---- */
        float s[8][4];
#pragma unroll
        for (int nt = 0; nt < 8; nt++) {
            s[nt][0] = 0.f; s[nt][1] = 0.f; s[nt][2] = 0.f; s[nt][3] = 0.f;
        }
#pragma unroll
        for (int ks = 0; ks < 8; ks++) {
#pragma unroll
            for (int nt2 = 0; nt2 < 4; nt2++) {
                uint32_t bf[4];
                ldsm_x4(bf, ksBase + bfOff + nt2 * 4352 + ks * 32);
                mma_tf32(s[2 * nt2],     qf[ks], bf[0], bf[1]);
                mma_tf32(s[2 * nt2 + 1], qf[ks], bf[2], bf[3]);
            }
        }

        /* ---- causal mask (diagonal tile only) ---- */
        if (kt == qt) {
            const int row0 = w * 16 + r0, row1 = row0 + 8;
#pragma unroll
            for (int nt = 0; nt < 8; nt++) {
                const int c0 = nt * 8 + 2 * a4, c1 = c0 + 1;
                if (c0 > row0) s[nt][0] = -1e30f;
                if (c1 > row0) s[nt][1] = -1e30f;
                if (c0 > row1) s[nt][2] = -1e30f;
                if (c1 > row1) s[nt][3] = -1e30f;
            }
        }

        /* ---- online softmax ---- */
        float mx0 = -1e30f, mx1 = -1e30f;
#pragma unroll
        for (int nt = 0; nt < 8; nt++) {
            mx0 = fmaxf(mx0, fmaxf(s[nt][0], s[nt][1]));
            mx1 = fmaxf(mx1, fmaxf(s[nt][2], s[nt][3]));
        }
        mx0 = fmaxf(mx0, __shfl_xor_sync(0xffffffffu, mx0, 1));
        mx0 = fmaxf(mx0, __shfl_xor_sync(0xffffffffu, mx0, 2));
        mx1 = fmaxf(mx1, __shfl_xor_sync(0xffffffffu, mx1, 1));
        mx1 = fmaxf(mx1, __shfl_xor_sync(0xffffffffu, mx1, 2));
        const float nm0 = fmaxf(mi0, mx0), nm1 = fmaxf(mi1, mx1);
        const float cr0 = __expf(mi0 - nm0), cr1 = __expf(mi1 - nm1);
        float sum0 = 0.f, sum1 = 0.f;
#pragma unroll
        for (int nt = 0; nt < 8; nt++) {
            s[nt][0] = __expf(s[nt][0] - nm0);
            s[nt][1] = __expf(s[nt][1] - nm0);
            s[nt][2] = __expf(s[nt][2] - nm1);
            s[nt][3] = __expf(s[nt][3] - nm1);
            sum0 += s[nt][0] + s[nt][1];
            sum1 += s[nt][2] + s[nt][3];
        }
        sum0 += __shfl_xor_sync(0xffffffffu, sum0, 1);
        sum0 += __shfl_xor_sync(0xffffffffu, sum0, 2);
        sum1 += __shfl_xor_sync(0xffffffffu, sum1, 1);
        sum1 += __shfl_xor_sync(0xffffffffu, sum1, 2);
        l0 = l0 * cr0 + sum0;  l1 = l1 * cr1 + sum1;
        mi0 = nm0;             mi1 = nm1;
#pragma unroll
        for (int nt = 0; nt < 8; nt++) {
            o[nt][0] *= cr0; o[nt][1] *= cr0;
            o[nt][2] *= cr1; o[nt][3] *= cr1;
        }

        __syncthreads();   /* all warps done reading Ks */

        /* ---- store P (tf32) into Ks alias ---- */
        {
            const int row0 = w * 16 + r0;
#pragma unroll
            for (int nt = 0; nt < 8; nt++) {
                const int c = nt * 8 + 2 * a4;
                Ks[row0 * ATS + c]           = f2tf32(s[nt][0]);
                Ks[row0 * ATS + c + 1]       = f2tf32(s[nt][1]);
                Ks[(row0 + 8) * ATS + c]     = f2tf32(s[nt][2]);
                Ks[(row0 + 8) * ATS + c + 1] = f2tf32(s[nt][3]);
            }
        }
        __syncthreads();

        /* ---- O += P @ V (ldmatrix A- and B-fragments) ---- */
#pragma unroll
        for (int ks = 0; ks < 8; ks++) {
            uint32_t pa[4];
            ldsm_x4(pa, ksBase + paOff + ks * 32);
#pragma unroll
            for (int nt2 = 0; nt2 < 4; nt2++) {
                uint32_t bf[4];
                ldsm_x4(bf, vtBase + bfOff + nt2 * 4352 + ks * 32);
                mma_tf32(o[2 * nt2],     pa, bf[0], bf[1]);
                mma_tf32(o[2 * nt2 + 1], pa, bf[2], bf[3]);
            }
        }
    }

    /* ---- finalize ---- */
    const float inv0 = 1.f / l0, inv1 = 1.f / l1;
    const size_t row0 = (size_t)(b * SEQ + qt * 64 + w * 16 + r0);
#pragma unroll
    for (int nt = 0; nt < 8; nt++) {
        const int col = h * HDIM + nt * 8 + 2 * a4;
        *(float2*)&Out[row0 * HIDDEN + col] =
            make_float2(o[nt][0] * inv0, o[nt][1] * inv0);
        *(float2*)&Out[(row0 + 8) * HIDDEN + col] =
            make_float2(o[nt][2] * inv1, o[nt][3] * inv1);
    }
}

/* ================================================================= */
extern "C" void kernel_launch(void* const* d_in, const int* in_sizes, int n_in,
                              void* d_out, int out_size)
{
    (void)in_sizes; (void)n_in; (void)out_size;
    const float* x  = (const float*)d_in[0];
    /* d_in[1] = causal mask, handled analytically */
    const float* Wq = (const float*)d_in[2];
    const float* bq = (const float*)d_in[3];
    const float* Wk = (const float*)d_in[4];
    const float* bk = (const float*)d_in[5];
    const float* Wv = (const float*)d_in[6];
    const float* bv = (const float*)d_in[7];
    const float* Wo = (const float*)d_in[8];
    const float* bo = (const float*)d_in[9];
    float* out = (float*)d_out;

    float *q, *k, *v, *attn;
    cudaGetSymbolAddress((void**)&q,    g_q);
    cudaGetSymbolAddress((void**)&k,    g_k);
    cudaGetSymbolAddress((void**)&v,    g_v);
    cudaGetSymbolAddress((void**)&attn, g_attn);

    /* fused Q/K/V projection */
    qkv_gemm<<<dim3(24, 16), 256>>>(x, Wq, bq, Wk, bk, Wv, bv);

    /* causal GQA attention (tensor cores + ldmatrix) */
    attn_tc<<<dim3(SEQ / 64, NHEADS, BATCH), 128>>>(q, k, v, attn);

    /* output projection */
    gemm_tf32<<<dim3(HIDDEN / 128, MTOT / 128), 256>>>(attn, Wo, bo, out,
                                                       HIDDEN, HIDDEN);
}

// round 5
// speedup vs baseline: 3.2419x; 1.0289x over previous
#include <cuda_runtime.h>
#include <math.h>
#include <stdint.h>

#define HIDDEN 2048
#define SEQ    1024
#define BATCH  2
#define NHEADS 32
#define NGROUP 8
#define HDIM   64
#define MTOT   (BATCH * SEQ)
#define KVW    (NGROUP * HDIM)   /* 512 */

/* ---------------- scratch (no cudaMalloc allowed) ---------------- */
__device__ float g_q[MTOT * HIDDEN];
__device__ float g_k[MTOT * KVW];
__device__ float g_v[MTOT * KVW];
__device__ float g_attn[MTOT * HIDDEN];

/* ---------------- helpers ---------------- */
__device__ __forceinline__ uint32_t f2tf32(float x) {
    uint32_t r;
    asm("cvt.rna.tf32.f32 %0, %1;" : "=r"(r) : "f"(x));
    return r;
}
__device__ __forceinline__ uint32_t smem_u32(const void* p) {
    uint32_t a;
    asm("{ .reg .u64 t; cvta.to.shared.u64 t, %1; cvt.u32.u64 %0, t; }"
        : "=r"(a) : "l"(p));
    return a;
}
__device__ __forceinline__ void mma_tf32(float* c, const uint32_t* a,
                                         uint32_t b0, uint32_t b1) {
    asm volatile(
        "mma.sync.aligned.m16n8k8.row.col.f32.tf32.tf32.f32 "
        "{%0,%1,%2,%3}, {%4,%5,%6,%7}, {%8,%9}, {%0,%1,%2,%3};"
        : "+f"(c[0]), "+f"(c[1]), "+f"(c[2]), "+f"(c[3])
        : "r"(a[0]), "r"(a[1]), "r"(a[2]), "r"(a[3]), "r"(b0), "r"(b1));
}
/* tf32 fragment via ldmatrix (b16 view): 4 regs from 4 lane-group addrs */
__device__ __forceinline__ void ldsm_x4(uint32_t* r, uint32_t addr) {
    asm volatile("ldmatrix.sync.aligned.m8n8.x4.shared.b16 {%0,%1,%2,%3}, [%4];"
        : "=r"(r[0]), "=r"(r[1]), "=r"(r[2]), "=r"(r[3]) : "r"(addr));
}
__device__ __forceinline__ void cvt_store4(uint32_t* dst, float4 v) {
    uint4 u;
    u.x = f2tf32(v.x); u.y = f2tf32(v.y);
    u.z = f2tf32(v.z); u.w = f2tf32(v.w);
    *(uint4*)dst = u;
}

/* =================================================================
 * TF32 NT GEMM: C[m,n] = sum_k A[m,k]*B[n,k] + bias[n]
 * 128x128 tile, BK=16, 256 threads (8 warps: 4m x 2n), warp 32x64.
 * Double-buffered smem (stride 20 floats = 80B -> conflict-free
 * LDSM row groups). Fragments via ldmatrix.x4, B-frags software-
 * pipelined. __launch_bounds__(256,2) -> 128 regs, 2 CTAs/SM.
 * ================================================================= */
#define GS 20

__device__ __forceinline__ void gemm_core(
    const float* __restrict__ A, const float* __restrict__ B,
    const float* __restrict__ bias, float* __restrict__ C,
    int ldc, int K, int m0, int n0)
{
    __shared__ uint32_t As[2][128 * GS];
    __shared__ uint32_t Bs[2][128 * GS];

    const int tid = threadIdx.x, lane = tid & 31, wid = tid >> 5;
    const int wm = (wid & 3) * 32, wn = (wid >> 2) * 64;

    const int grp = lane >> 3;
    const uint32_t aOff = (uint32_t)(wm + (lane & 7) + ((grp & 1) << 3)) * 80
                        + (uint32_t)(grp >> 1) * 16;
    const uint32_t bOff = (uint32_t)(wn + (lane & 7) + ((grp >> 1) << 3)) * 80
                        + (uint32_t)(grp & 1) * 16;

    float acc[2][8][4];
#pragma unroll
    for (int mt = 0; mt < 2; mt++)
#pragma unroll
        for (int nt = 0; nt < 8; nt++) {
            acc[mt][nt][0] = 0.f; acc[mt][nt][1] = 0.f;
            acc[mt][nt][2] = 0.f; acc[mt][nt][3] = 0.f;
        }

    const int lr = tid >> 1, lc = (tid & 1) * 8;
    const float* Ag = A + (size_t)(m0 + lr) * K + lc;
    const float* Bg = B + (size_t)(n0 + lr) * K + lc;
    const int so = lr * GS + lc;

    /* prologue: tile 0 */
    {
        float4 a0 = *(const float4*)Ag, a1 = *(const float4*)(Ag + 4);
        float4 b0 = *(const float4*)Bg, b1 = *(const float4*)(Bg + 4);
        cvt_store4(&As[0][so], a0); cvt_store4(&As[0][so + 4], a1);
        cvt_store4(&Bs[0][so], b0); cvt_store4(&Bs[0][so + 4], b1);
    }
    __syncthreads();

    const int nIter = K >> 4;
    for (int it = 0; it < nIter; it++) {
        const int cur = it & 1;
        float4 pa0, pa1, pb0, pb1;
        if (it + 1 < nIter) {
            const float* Ap = Ag + (it + 1) * 16;
            const float* Bp = Bg + (it + 1) * 16;
            pa0 = *(const float4*)Ap; pa1 = *(const float4*)(Ap + 4);
            pb0 = *(const float4*)Bp; pb1 = *(const float4*)(Bp + 4);
        }
        const uint32_t aBase = smem_u32(&As[cur][0]);
        const uint32_t bBase = smem_u32(&Bs[cur][0]);
#pragma unroll
        for (int ks = 0; ks < 2; ks++) {
            uint32_t af[2][4];
            ldsm_x4(af[0], aBase + aOff + ks * 32);          /* mt=0 */
            ldsm_x4(af[1], aBase + aOff + 1280 + ks * 32);   /* mt=1 */
            /* software-pipelined B fragments */
            uint32_t bf[2][4];
            ldsm_x4(bf[0], bBase + bOff + ks * 32);          /* nt2=0 */
#pragma unroll
            for (int nt2 = 0; nt2 < 4; nt2++) {
                const int c = nt2 & 1, n = 1 - c;
                if (nt2 < 3)
                    ldsm_x4(bf[n], bBase + bOff + (nt2 + 1) * 1280 + ks * 32);
                mma_tf32(acc[0][2 * nt2],     af[0], bf[c][0], bf[c][1]);
                mma_tf32(acc[0][2 * nt2 + 1], af[0], bf[c][2], bf[c][3]);
                mma_tf32(acc[1][2 * nt2],     af[1], bf[c][0], bf[c][1]);
                mma_tf32(acc[1][2 * nt2 + 1], af[1], bf[c][2], bf[c][3]);
            }
        }
        if (it + 1 < nIter) {
            const int nxt = 1 - cur;
            cvt_store4(&As[nxt][so], pa0); cvt_store4(&As[nxt][so + 4], pa1);
            cvt_store4(&Bs[nxt][so], pb0); cvt_store4(&Bs[nxt][so + 4], pb1);
        }
        __syncthreads();
    }

    /* epilogue: bias + float2 stores */
    const int r0 = lane >> 2, a4 = lane & 3;
#pragma unroll
    for (int mt = 0; mt < 2; mt++) {
#pragma unroll
        for (int nt = 0; nt < 8; nt++) {
            const int col = n0 + wn + nt * 8 + 2 * a4;
            const float b0 = bias[col], b1 = bias[col + 1];
            const int rA = m0 + wm + mt * 16 + r0;
            float2 v0 = make_float2(acc[mt][nt][0] + b0, acc[mt][nt][1] + b1);
            float2 v1 = make_float2(acc[mt][nt][2] + b0, acc[mt][nt][3] + b1);
            *(float2*)&C[(size_t)rA * ldc + col] = v0;
            *(float2*)&C[(size_t)(rA + 8) * ldc + col] = v1;
        }
    }
}

/* fused QKV projection: grid (24, 16) */
__global__ __launch_bounds__(256, 2) void qkv_gemm(
    const float* __restrict__ x,
    const float* __restrict__ Wq, const float* __restrict__ bq,
    const float* __restrict__ Wk, const float* __restrict__ bk,
    const float* __restrict__ Wv, const float* __restrict__ bv)
{
    const int bx = blockIdx.x;
    const float* B; const float* bias; float* C; int ldc; int n0;
    if (bx < 16)      { B = Wq; bias = bq; C = g_q; ldc = HIDDEN; n0 = bx * 128; }
    else if (bx < 20) { B = Wk; bias = bk; C = g_k; ldc = KVW;    n0 = (bx - 16) * 128; }
    else              { B = Wv; bias = bv; C = g_v; ldc = KVW;    n0 = (bx - 20) * 128; }
    gemm_core(x, B, bias, C, ldc, HIDDEN, blockIdx.y * 128, n0);
}

/* generic GEMM (O-projection): grid (N/128, M/128) */
__global__ __launch_bounds__(256, 2) void gemm_tf32(
    const float* __restrict__ A, const float* __restrict__ B,
    const float* __restrict__ bias, float* __restrict__ C,
    int ldc, int K)
{
    gemm_core(A, B, bias, C, ldc, K, blockIdx.y * 128, blockIdx.x * 128);
}

/* =================================================================
 * Tensor-core flash attention (causal, GQA), mma.sync tf32 +
 * ldmatrix fragments. Block 128 threads (4 warps x 16 query rows).
 * smem: Ks[64][68] (aliased with P), Vt[64][68] transposed.
 * ================================================================= */
#define ATS 68

__global__ __launch_bounds__(128) void attn_tc(
    const float* __restrict__ Q, const float* __restrict__ Kp,
    const float* __restrict__ Vp, float* __restrict__ Out)
{
    __shared__ uint32_t Ks[64 * ATS];
    __shared__ uint32_t Vt[64 * ATS];

    const int qt = blockIdx.x, h = blockIdx.y, b = blockIdx.z, g = h >> 2;
    const int tid = threadIdx.x, lane = tid & 31, w = tid >> 5;
    const int r0 = lane >> 2, a4 = lane & 3;

    const int grp = lane >> 3;
    const uint32_t paOff = (uint32_t)(w * 16 + (lane & 7) + ((grp & 1) << 3)) * 272
                         + (uint32_t)(grp >> 1) * 16;
    const uint32_t bfOff = (uint32_t)((lane & 7) + ((grp >> 1) << 3)) * 272
                         + (uint32_t)(grp & 1) * 16;
    const uint32_t ksBase = smem_u32(Ks);
    const uint32_t vtBase = smem_u32(Vt);

    uint32_t qf[8][4];
    {
        const float sc = 0.125f;
        const float* qp = Q + (size_t)(b * SEQ + qt * 64 + w * 16) * HIDDEN + h * HDIM;
#pragma unroll
        for (int ks = 0; ks < 8; ks++) {
            const int c = ks * 8 + a4;
            qf[ks][0] = f2tf32(qp[(size_t)r0 * HIDDEN + c] * sc);
            qf[ks][1] = f2tf32(qp[(size_t)(r0 + 8) * HIDDEN + c] * sc);
            qf[ks][2] = f2tf32(qp[(size_t)r0 * HIDDEN + c + 4] * sc);
            qf[ks][3] = f2tf32(qp[(size_t)(r0 + 8) * HIDDEN + c + 4] * sc);
        }
    }

    float o[8][4];
#pragma unroll
    for (int nt = 0; nt < 8; nt++) {
        o[nt][0] = 0.f; o[nt][1] = 0.f; o[nt][2] = 0.f; o[nt][3] = 0.f;
    }
    float mi0 = -1e30f, mi1 = -1e30f, l0 = 0.f, l1 = 0.f;

    const int lrow = tid >> 1;
    const int lcb  = (tid & 1) * 32;

    for (int kt = 0; kt <= qt; kt++) {
        __syncthreads();
        {
            const size_t base = (size_t)(b * SEQ + kt * 64 + lrow) * KVW + g * HDIM + lcb;
            const float* kp = Kp + base;
            const float* vp = Vp + base;
#pragma unroll
            for (int u = 0; u < 8; u++) {
                float4 kv = *(const float4*)(kp + u * 4);
                cvt_store4(&Ks[lrow * ATS + lcb + u * 4], kv);
                float4 vv = *(const float4*)(vp + u * 4);
                const int c = lcb + u * 4;
                Vt[(c + 0) * ATS + lrow] = f2tf32(vv.x);
                Vt[(c + 1) * ATS + lrow] = f2tf32(vv.y);
                Vt[(c + 2) * ATS + lrow] = f2tf32(vv.z);
                Vt[(c + 3) * ATS + lrow] = f2tf32(vv.w);
            }
        }
        __syncthreads();

        float s[8][4];
#pragma unroll
        for (int nt = 0; nt < 8; nt++) {
            s[nt][0] = 0.f; s[nt][1] = 0.f; s[nt][2] = 0.f; s[nt][3] = 0.f;
        }
#pragma unroll
        for (int ks = 0; ks < 8; ks++) {
#pragma unroll
            for (int nt2 = 0; nt2 < 4; nt2++) {
                uint32_t bf[4];
                ldsm_x4(bf, ksBase + bfOff + nt2 * 4352 + ks * 32);
                mma_tf32(s[2 * nt2],     qf[ks], bf[0], bf[1]);
                mma_tf32(s[2 * nt2 + 1], qf[ks], bf[2], bf[3]);
            }
        }

        if (kt == qt) {
            const int row0 = w * 16 + r0, row1 = row0 + 8;
#pragma unroll
            for (int nt = 0; nt < 8; nt++) {
                const int c0 = nt * 8 + 2 * a4, c1 = c0 + 1;
                if (c0 > row0) s[nt][0] = -1e30f;
                if (c1 > row0) s[nt][1] = -1e30f;
                if (c0 > row1) s[nt][2] = -1e30f;
                if (c1 > row1) s[nt][3] = -1e30f;
            }
        }

        float mx0 = -1e30f, mx1 = -1e30f;
#pragma unroll
        for (int nt = 0; nt < 8; nt++) {
            mx0 = fmaxf(mx0, fmaxf(s[nt][0], s[nt][1]));
            mx1 = fmaxf(mx1, fmaxf(s[nt][2], s[nt][3]));
        }
        mx0 = fmaxf(mx0, __shfl_xor_sync(0xffffffffu, mx0, 1));
        mx0 = fmaxf(mx0, __shfl_xor_sync(0xffffffffu, mx0, 2));
        mx1 = fmaxf(mx1, __shfl_xor_sync(0xffffffffu, mx1, 1));
        mx1 = fmaxf(mx1, __shfl_xor_sync(0xffffffffu, mx1, 2));
        const float nm0 = fmaxf(mi0, mx0), nm1 = fmaxf(mi1, mx1);
        const float cr0 = __expf(mi0 - nm0), cr1 = __expf(mi1 - nm1);
        float sum0 = 0.f, sum1 = 0.f;
#pragma unroll
        for (int nt = 0; nt < 8; nt++) {
            s[nt][0] = __expf(s[nt][0] - nm0);
            s[nt][1] = __expf(s[nt][1] - nm0);
            s[nt][2] = __expf(s[nt][2] - nm1);
            s[nt][3] = __expf(s[nt][3] - nm1);
            sum0 += s[nt][0] + s[nt][1];
            sum1 += s[nt][2] + s[nt][3];
        }
        sum0 += __shfl_xor_sync(0xffffffffu, sum0, 1);
        sum0 += __shfl_xor_sync(0xffffffffu, sum0, 2);
        sum1 += __shfl_xor_sync(0xffffffffu, sum1, 1);
        sum1 += __shfl_xor_sync(0xffffffffu, sum1, 2);
        l0 = l0 * cr0 + sum0;  l1 = l1 * cr1 + sum1;
        mi0 = nm0;             mi1 = nm1;
#pragma unroll
        for (int nt = 0; nt < 8; nt++) {
            o[nt][0] *= cr0; o[nt][1] *= cr0;
            o[nt][2] *= cr1; o[nt][3] *= cr1;
        }

        __syncthreads();
        {
            const int row0 = w * 16 + r0;
#pragma unroll
            for (int nt = 0; nt < 8; nt++) {
                const int c = nt * 8 + 2 * a4;
                Ks[row0 * ATS + c]           = f2tf32(s[nt][0]);
                Ks[row0 * ATS + c + 1]       = f2tf32(s[nt][1]);
                Ks[(row0 + 8) * ATS + c]     = f2tf32(s[nt][2]);
                Ks[(row0 + 8) * ATS + c + 1] = f2tf32(s[nt][3]);
            }
        }
        __syncthreads();

#pragma unroll
        for (int ks = 0; ks < 8; ks++) {
            uint32_t pa[4];
            ldsm_x4(pa, ksBase + paOff + ks * 32);
#pragma unroll
            for (int nt2 = 0; nt2 < 4; nt2++) {
                uint32_t bf[4];
                ldsm_x4(bf, vtBase + bfOff + nt2 * 4352 + ks * 32);
                mma_tf32(o[2 * nt2],     pa, bf[0], bf[1]);
                mma_tf32(o[2 * nt2 + 1], pa, bf[2], bf[3]);
            }
        }
    }

    const float inv0 = 1.f / l0, inv1 = 1.f / l1;
    const size_t row0 = (size_t)(b * SEQ + qt * 64 + w * 16 + r0);
#pragma unroll
    for (int nt = 0; nt < 8; nt++) {
        const int col = h * HDIM + nt * 8 + 2 * a4;
        *(float2*)&Out[row0 * HIDDEN + col] =
            make_float2(o[nt][0] * inv0, o[nt][1] * inv0);
        *(float2*)&Out[(row0 + 8) * HIDDEN + col] =
            make_float2(o[nt][2] * inv1, o[nt][3] * inv1);
    }
}

/* ================================================================= */
extern "C" void kernel_launch(void* const* d_in, const int* in_sizes, int n_in,
                              void* d_out, int out_size)
{
    (void)in_sizes; (void)n_in; (void)out_size;
    const float* x  = (const float*)d_in[0];
    /* d_in[1] = causal mask, handled analytically */
    const float* Wq = (const float*)d_in[2];
    const float* bq = (const float*)d_in[3];
    const float* Wk = (const float*)d_in[4];
    const float* bk = (const float*)d_in[5];
    const float* Wv = (const float*)d_in[6];
    const float* bv = (const float*)d_in[7];
    const float* Wo = (const float*)d_in[8];
    const float* bo = (const float*)d_in[9];
    float* out = (float*)d_out;

    float *q, *k, *v, *attn;
    cudaGetSymbolAddress((void**)&q,    g_q);
    cudaGetSymbolAddress((void**)&k,    g_k);
    cudaGetSymbolAddress((void**)&v,    g_v);
    cudaGetSymbolAddress((void**)&attn, g_attn);

    /* fused Q/K/V projection */
    qkv_gemm<<<dim3(24, 16), 256>>>(x, Wq, bq, Wk, bk, Wv, bv);

    /* causal GQA attention (tensor cores + ldmatrix) */
    attn_tc<<<dim3(SEQ / 64, NHEADS, BATCH), 128>>>(q, k, v, attn);

    /* output projection */
    gemm_tf32<<<dim3(HIDDEN / 128, MTOT / 128), 256>>>(attn, Wo, bo, out,
                                                       HIDDEN, HIDDEN);
}

// round 6
// speedup vs baseline: 3.2584x; 1.0051x over previous
#include <cuda_runtime.h>
#include <math.h>
#include <stdint.h>

#define HIDDEN 2048
#define SEQ    1024
#define BATCH  2
#define NHEADS 32
#define NGROUP 8
#define HDIM   64
#define MTOT   (BATCH * SEQ)
#define KVW    (NGROUP * HDIM)   /* 512 */

/* ---------------- scratch (no cudaMalloc allowed) ---------------- */
__device__ float g_xt [MTOT * HIDDEN];            /* tf32 bits of x   */
__device__ float g_wt [(HIDDEN + 2 * KVW) * HIDDEN]; /* Wq|Wk|Wv tf32 */
__device__ float g_wot[HIDDEN * HIDDEN];          /* Wo tf32          */
__device__ float g_q  [MTOT * HIDDEN];
__device__ float g_k  [MTOT * KVW];
__device__ float g_v  [MTOT * KVW];
__device__ float g_attn[MTOT * HIDDEN];           /* tf32 bits        */

/* ---------------- helpers ---------------- */
__device__ __forceinline__ uint32_t f2tf32(float x) {
    uint32_t r;
    asm("cvt.rna.tf32.f32 %0, %1;" : "=r"(r) : "f"(x));
    return r;
}
__device__ __forceinline__ uint32_t smem_u32(const void* p) {
    uint32_t a;
    asm("{ .reg .u64 t; cvta.to.shared.u64 t, %1; cvt.u32.u64 %0, t; }"
        : "=r"(a) : "l"(p));
    return a;
}
__device__ __forceinline__ void mma_tf32(float* c, const uint32_t* a,
                                         uint32_t b0, uint32_t b1) {
    asm volatile(
        "mma.sync.aligned.m16n8k8.row.col.f32.tf32.tf32.f32 "
        "{%0,%1,%2,%3}, {%4,%5,%6,%7}, {%8,%9}, {%0,%1,%2,%3};"
        : "+f"(c[0]), "+f"(c[1]), "+f"(c[2]), "+f"(c[3])
        : "r"(a[0]), "r"(a[1]), "r"(a[2]), "r"(a[3]), "r"(b0), "r"(b1));
}
__device__ __forceinline__ void ldsm_x4(uint32_t* r, uint32_t addr) {
    asm volatile("ldmatrix.sync.aligned.m8n8.x4.shared.b16 {%0,%1,%2,%3}, [%4];"
        : "=r"(r[0]), "=r"(r[1]), "=r"(r[2]), "=r"(r[3]) : "r"(addr));
}
__device__ __forceinline__ void cp16(uint32_t dst, const void* src) {
    asm volatile("cp.async.cg.shared.global [%0], [%1], 16;"
                 :: "r"(dst), "l"(src));
}
#define CP_COMMIT() asm volatile("cp.async.commit_group;" ::: "memory")
#define CP_WAIT1()  asm volatile("cp.async.wait_group 1;"  ::: "memory")

/* =================================================================
 * Pre-convert x, Wq|Wk|Wv, Wo to tf32 bits (grid-stride, float4).
 * ================================================================= */
__global__ void cvt_all(const float4* __restrict__ x,
                        const float4* __restrict__ wq,
                        const float4* __restrict__ wk,
                        const float4* __restrict__ wv,
                        const float4* __restrict__ wo)
{
    const int64_t N0 = 1048576;          /* x  : 4M floats  */
    const int64_t N1 = N0 + 1048576;     /* Wq : 4M         */
    const int64_t N2 = N1 + 262144;      /* Wk : 1M         */
    const int64_t N3 = N2 + 262144;      /* Wv : 1M         */
    const int64_t N4 = N3 + 1048576;     /* Wo : 4M         */
    uint4* xt  = (uint4*)g_xt;
    uint4* wt  = (uint4*)g_wt;
    uint4* wot = (uint4*)g_wot;
    for (int64_t i = (int64_t)blockIdx.x * blockDim.x + threadIdx.x;
         i < N4; i += (int64_t)gridDim.x * blockDim.x) {
        float4 v; uint4* dst;
        if (i < N0)      { v = x [i];      dst = xt  + i; }
        else if (i < N1) { v = wq[i - N0]; dst = wt  + (i - N0); }
        else if (i < N2) { v = wk[i - N1]; dst = wt  + 1048576 + (i - N1); }
        else if (i < N3) { v = wv[i - N2]; dst = wt  + 1310720 + (i - N2); }
        else             { v = wo[i - N3]; dst = wot + (i - N3); }
        uint4 u;
        u.x = f2tf32(v.x); u.y = f2tf32(v.y);
        u.z = f2tf32(v.z); u.w = f2tf32(v.w);
        *dst = u;
    }
}

/* =================================================================
 * TF32 NT GEMM, cp.async 3-stage: C[m,n] = sum_k A[m,k]*B[n,k]+bias
 * CTA 128x128, 128 threads (4 warps 2x2), warp tile 64x64, BK=16.
 * A,B pre-converted tf32 bits. smem rows padded to 80B (LDSM clean).
 * ================================================================= */
#define BK    16
#define ROWB  80                       /* bytes per padded row      */
#define STA   (128 * ROWB)             /* 10240: one 128x16 tile    */
#define STAGE (2 * STA)                /* A + B                     */
#define NST   3
#define GEMM_SMEM (NST * STAGE)        /* 61440                     */

__device__ __forceinline__ void gemm_core(
    const float* __restrict__ A, const float* __restrict__ Bm,
    const float* __restrict__ bias, float* __restrict__ C,
    int ldc, int K, int m0, int n0B, int n0C)
{
    extern __shared__ char smem[];
    const uint32_t sb = smem_u32(smem);
    const int tid = threadIdx.x, lane = tid & 31, wid = tid >> 5;
    const int wm = (wid & 1) * 64, wn = (wid >> 1) * 64;
    const int grp = lane >> 3;
    const uint32_t aOff = (uint32_t)(wm + (lane & 7) + ((grp & 1) << 3)) * ROWB
                        + (uint32_t)(grp >> 1) * 16;
    const uint32_t bOff = (uint32_t)(wn + (lane & 7) + ((grp >> 1) << 3)) * ROWB
                        + (uint32_t)(grp & 1) * 16;

    float acc[4][8][4];
#pragma unroll
    for (int mt = 0; mt < 4; mt++)
#pragma unroll
        for (int nt = 0; nt < 8; nt++) {
            acc[mt][nt][0] = 0.f; acc[mt][nt][1] = 0.f;
            acc[mt][nt][2] = 0.f; acc[mt][nt][3] = 0.f;
        }

    const float* Ag = A  + (size_t)(m0  + tid) * K;
    const float* Bg = Bm + (size_t)(n0B + tid) * K;
    const uint32_t sRow = (uint32_t)tid * ROWB;
    const int nIter = K / BK;

    /* prologue: stages 0,1 */
#pragma unroll
    for (int s = 0; s < NST - 1; s++) {
        const uint32_t st = sb + s * STAGE;
#pragma unroll
        for (int i = 0; i < 4; i++) {
            cp16(st + sRow + i * 16,       Ag + s * BK + i * 4);
            cp16(st + STA + sRow + i * 16, Bg + s * BK + i * 4);
        }
        CP_COMMIT();
    }

    int cur = 0;
    for (int it = 0; it < nIter; it++) {
        CP_WAIT1();            /* stage it ready */
        __syncthreads();       /* also: everyone done with stage it-1 */
        if (it + NST - 1 < nIter) {
            const uint32_t st = sb + ((it + NST - 1) % NST) * STAGE;
            const int k0 = (it + NST - 1) * BK;
#pragma unroll
            for (int i = 0; i < 4; i++) {
                cp16(st + sRow + i * 16,       Ag + k0 + i * 4);
                cp16(st + STA + sRow + i * 16, Bg + k0 + i * 4);
            }
        }
        CP_COMMIT();

        const uint32_t aB = sb + cur * STAGE;
        const uint32_t bB = aB + STA;
#pragma unroll
        for (int ks = 0; ks < 2; ks++) {
            uint32_t af[4][4];
#pragma unroll
            for (int mt = 0; mt < 4; mt++)
                ldsm_x4(af[mt], aB + aOff + mt * (16 * ROWB) + ks * 32);
            uint32_t bf[2][4];
            ldsm_x4(bf[0], bB + bOff + ks * 32);
#pragma unroll
            for (int nt2 = 0; nt2 < 4; nt2++) {
                const int c = nt2 & 1, n = 1 - c;
                if (nt2 < 3)
                    ldsm_x4(bf[n], bB + bOff + (nt2 + 1) * (16 * ROWB) + ks * 32);
#pragma unroll
                for (int mt = 0; mt < 4; mt++) {
                    mma_tf32(acc[mt][2 * nt2],     af[mt], bf[c][0], bf[c][1]);
                    mma_tf32(acc[mt][2 * nt2 + 1], af[mt], bf[c][2], bf[c][3]);
                }
            }
        }
        cur++; if (cur == NST) cur = 0;
    }

    /* epilogue: bias + float2 stores */
    const int r0 = lane >> 2, a4 = lane & 3;
#pragma unroll
    for (int mt = 0; mt < 4; mt++) {
#pragma unroll
        for (int nt = 0; nt < 8; nt++) {
            const int col = n0C + wn + nt * 8 + 2 * a4;
            const float b0 = bias[col], b1 = bias[col + 1];
            const int rA = m0 + wm + mt * 16 + r0;
            *(float2*)&C[(size_t)rA * ldc + col] =
                make_float2(acc[mt][nt][0] + b0, acc[mt][nt][1] + b1);
            *(float2*)&C[(size_t)(rA + 8) * ldc + col] =
                make_float2(acc[mt][nt][2] + b0, acc[mt][nt][3] + b1);
        }
    }
}

/* fused QKV projection: grid (24, 16) */
__global__ __launch_bounds__(128, 2) void qkv_gemm(
    const float* __restrict__ bq, const float* __restrict__ bk,
    const float* __restrict__ bv)
{
    const int n0 = blockIdx.x * 128, m0 = blockIdx.y * 128;
    const float* bias; float* C; int ldc, n0C;
    if (n0 < 2048)      { C = g_q; ldc = HIDDEN; bias = bq; n0C = n0; }
    else if (n0 < 2560) { C = g_k; ldc = KVW;    bias = bk; n0C = n0 - 2048; }
    else                { C = g_v; ldc = KVW;    bias = bv; n0C = n0 - 2560; }
    gemm_core(g_xt, g_wt, bias, C, ldc, HIDDEN, m0, n0, n0C);
}

/* O projection: grid (16, 16) */
__global__ __launch_bounds__(128, 2) void oproj_gemm(
    const float* __restrict__ bo, float* __restrict__ out)
{
    gemm_core(g_attn, g_wot, bo, out, HIDDEN, HIDDEN,
              blockIdx.y * 128, blockIdx.x * 128, blockIdx.x * 128);
}

/* =================================================================
 * Flash attention (causal, GQA): 128 q-rows per CTA, 256 threads
 * (8 warps x 16 rows), 64-col K tiles, mma.sync tf32 + ldmatrix.
 * smem: [Ks 64x68][Pext 64x68][Vt 64x68]; P = 128 rows over Ks+Pext.
 * ================================================================= */
#define ATS 68
#define ATT_SMEM (3 * 64 * ATS * 4)   /* 52224 B */

__global__ __launch_bounds__(256, 2) void attn_tc(
    const float* __restrict__ Q, const float* __restrict__ Kp,
    const float* __restrict__ Vp, float* __restrict__ Out)
{
    extern __shared__ uint32_t sm[];
    uint32_t* Ks = sm;                     /* rows 0..63; P rows 0..127 */
    uint32_t* Vt = sm + 2 * 64 * ATS;      /* rows 0..63 (d-major)      */

    const int qt = (int)gridDim.x - 1 - (int)blockIdx.x;  /* longest first */
    const int h = blockIdx.y, b = blockIdx.z, g = h >> 2;
    const int tid = threadIdx.x, lane = tid & 31, w = tid >> 5;
    const int r0 = lane >> 2, a4 = lane & 3;

    const int grp = lane >> 3;
    const uint32_t paOff = (uint32_t)(w * 16 + (lane & 7) + ((grp & 1) << 3)) * 272
                         + (uint32_t)(grp >> 1) * 16;
    const uint32_t bfOff = (uint32_t)((lane & 7) + ((grp >> 1) << 3)) * 272
                         + (uint32_t)(grp & 1) * 16;
    const uint32_t ksBase = smem_u32(sm);
    const uint32_t vtBase = ksBase + 2 * 64 * ATS * 4;

    /* ---- hoist Q fragments (scaled, tf32) ---- */
    uint32_t qf[8][4];
    {
        const float sc = 0.125f;
        const float* qp = Q + (size_t)(b * SEQ + qt * 128 + w * 16) * HIDDEN + h * HDIM;
#pragma unroll
        for (int ks = 0; ks < 8; ks++) {
            const int c = ks * 8 + a4;
            qf[ks][0] = f2tf32(qp[(size_t)r0 * HIDDEN + c] * sc);
            qf[ks][1] = f2tf32(qp[(size_t)(r0 + 8) * HIDDEN + c] * sc);
            qf[ks][2] = f2tf32(qp[(size_t)r0 * HIDDEN + c + 4] * sc);
            qf[ks][3] = f2tf32(qp[(size_t)(r0 + 8) * HIDDEN + c + 4] * sc);
        }
    }

    float o[8][4];
#pragma unroll
    for (int nt = 0; nt < 8; nt++) {
        o[nt][0] = 0.f; o[nt][1] = 0.f; o[nt][2] = 0.f; o[nt][3] = 0.f;
    }
    float mi0 = -1e30f, mi1 = -1e30f, l0 = 0.f, l1 = 0.f;

    const int lrow = tid >> 2;          /* 0..63 */
    const int lcb  = (tid & 3) * 16;    /* 0,16,32,48 */
    const int ktEnd = 2 * qt + 1;

    for (int kt = 0; kt <= ktEnd; kt++) {
        __syncthreads();   /* prior P/V consumers done */

        /* ---- stage K (row-major) + V (transposed), tf32 ---- */
        {
            const size_t base = (size_t)(b * SEQ + kt * 64 + lrow) * KVW + g * HDIM + lcb;
            const float* kp = Kp + base;
            const float* vp = Vp + base;
#pragma unroll
            for (int u = 0; u < 4; u++) {
                float4 kv = *(const float4*)(kp + u * 4);
                uint32_t* kd = &Ks[lrow * ATS + lcb + u * 4];
                kd[0] = f2tf32(kv.x); kd[1] = f2tf32(kv.y);
                kd[2] = f2tf32(kv.z); kd[3] = f2tf32(kv.w);
                float4 vv = *(const float4*)(vp + u * 4);
                const int c = lcb + u * 4;
                Vt[(c + 0) * ATS + lrow] = f2tf32(vv.x);
                Vt[(c + 1) * ATS + lrow] = f2tf32(vv.y);
                Vt[(c + 2) * ATS + lrow] = f2tf32(vv.z);
                Vt[(c + 3) * ATS + lrow] = f2tf32(vv.w);
            }
        }
        __syncthreads();

        /* ---- S = Q K^T ---- */
        float s[8][4];
#pragma unroll
        for (int nt = 0; nt < 8; nt++) {
            s[nt][0] = 0.f; s[nt][1] = 0.f; s[nt][2] = 0.f; s[nt][3] = 0.f;
        }
#pragma unroll
        for (int ks = 0; ks < 8; ks++) {
#pragma unroll
            for (int nt2 = 0; nt2 < 4; nt2++) {
                uint32_t bf[4];
                ldsm_x4(bf, ksBase + bfOff + nt2 * 4352 + ks * 32);
                mma_tf32(s[2 * nt2],     qf[ks], bf[0], bf[1]);
                mma_tf32(s[2 * nt2 + 1], qf[ks], bf[2], bf[3]);
            }
        }

        /* ---- causal mask (two diagonal-band tiles) ---- */
        if (kt >= 2 * qt) {
            const int diff  = (kt - 2 * qt) * 64;
            const int row0g = w * 16 + r0, row1g = row0g + 8;
#pragma unroll
            for (int nt = 0; nt < 8; nt++) {
                const int c0 = nt * 8 + 2 * a4 + diff, c1 = c0 + 1;
                if (c0 > row0g) s[nt][0] = -1e30f;
                if (c1 > row0g) s[nt][1] = -1e30f;
                if (c0 > row1g) s[nt][2] = -1e30f;
                if (c1 > row1g) s[nt][3] = -1e30f;
            }
        }

        /* ---- online softmax (rows r0, r0+8; quad shfl reduce) ---- */
        float mx0 = -1e30f, mx1 = -1e30f;
#pragma unroll
        for (int nt = 0; nt < 8; nt++) {
            mx0 = fmaxf(mx0, fmaxf(s[nt][0], s[nt][1]));
            mx1 = fmaxf(mx1, fmaxf(s[nt][2], s[nt][3]));
        }
        mx0 = fmaxf(mx0, __shfl_xor_sync(0xffffffffu, mx0, 1));
        mx0 = fmaxf(mx0, __shfl_xor_sync(0xffffffffu, mx0, 2));
        mx1 = fmaxf(mx1, __shfl_xor_sync(0xffffffffu, mx1, 1));
        mx1 = fmaxf(mx1, __shfl_xor_sync(0xffffffffu, mx1, 2));
        const float nm0 = fmaxf(mi0, mx0), nm1 = fmaxf(mi1, mx1);
        const float cr0 = __expf(mi0 - nm0), cr1 = __expf(mi1 - nm1);
        float sum0 = 0.f, sum1 = 0.f;
#pragma unroll
        for (int nt = 0; nt < 8; nt++) {
            s[nt][0] = __expf(s[nt][0] - nm0);
            s[nt][1] = __expf(s[nt][1] - nm0);
            s[nt][2] = __expf(s[nt][2] - nm1);
            s[nt][3] = __expf(s[nt][3] - nm1);
            sum0 += s[nt][0] + s[nt][1];
            sum1 += s[nt][2] + s[nt][3];
        }
        sum0 += __shfl_xor_sync(0xffffffffu, sum0, 1);
        sum0 += __shfl_xor_sync(0xffffffffu, sum0, 2);
        sum1 += __shfl_xor_sync(0xffffffffu, sum1, 1);
        sum1 += __shfl_xor_sync(0xffffffffu, sum1, 2);
        l0 = l0 * cr0 + sum0;  l1 = l1 * cr1 + sum1;
        mi0 = nm0;             mi1 = nm1;
#pragma unroll
        for (int nt = 0; nt < 8; nt++) {
            o[nt][0] *= cr0; o[nt][1] *= cr0;
            o[nt][2] *= cr1; o[nt][3] *= cr1;
        }

        __syncthreads();   /* all warps done reading Ks before P overwrite */

        /* ---- store P rows (own warp's 16 rows, tf32) ---- */
        {
            const int row0 = w * 16 + r0;
#pragma unroll
            for (int nt = 0; nt < 8; nt++) {
                const int c = nt * 8 + 2 * a4;
                sm[row0 * ATS + c]           = f2tf32(s[nt][0]);
                sm[row0 * ATS + c + 1]       = f2tf32(s[nt][1]);
                sm[(row0 + 8) * ATS + c]     = f2tf32(s[nt][2]);
                sm[(row0 + 8) * ATS + c + 1] = f2tf32(s[nt][3]);
            }
        }
        __syncwarp();      /* PV reads only own warp's P rows */

        /* ---- O += P @ V ---- */
#pragma unroll
        for (int ks = 0; ks < 8; ks++) {
            uint32_t pa[4];
            ldsm_x4(pa, ksBase + paOff + ks * 32);
#pragma unroll
            for (int nt2 = 0; nt2 < 4; nt2++) {
                uint32_t bf[4];
                ldsm_x4(bf, vtBase + bfOff + nt2 * 4352 + ks * 32);
                mma_tf32(o[2 * nt2],     pa, bf[0], bf[1]);
                mma_tf32(o[2 * nt2 + 1], pa, bf[2], bf[3]);
            }
        }
    }

    /* ---- finalize: /l, round to tf32 bits for cp.async O-proj ---- */
    const float inv0 = 1.f / l0, inv1 = 1.f / l1;
    const size_t row0 = (size_t)(b * SEQ + qt * 128 + w * 16 + r0);
#pragma unroll
    for (int nt = 0; nt < 8; nt++) {
        const int col = h * HDIM + nt * 8 + 2 * a4;
        *(float2*)&Out[row0 * HIDDEN + col] = make_float2(
            __uint_as_float(f2tf32(o[nt][0] * inv0)),
            __uint_as_float(f2tf32(o[nt][1] * inv0)));
        *(float2*)&Out[(row0 + 8) * HIDDEN + col] = make_float2(
            __uint_as_float(f2tf32(o[nt][2] * inv1)),
            __uint_as_float(f2tf32(o[nt][3] * inv1)));
    }
}

/* ================================================================= */
extern "C" void kernel_launch(void* const* d_in, const int* in_sizes, int n_in,
                              void* d_out, int out_size)
{
    (void)in_sizes; (void)n_in; (void)out_size;
    const float* x  = (const float*)d_in[0];
    /* d_in[1] = causal mask, handled analytically */
    const float* Wq = (const float*)d_in[2];
    const float* bq = (const float*)d_in[3];
    const float* Wk = (const float*)d_in[4];
    const float* bk = (const float*)d_in[5];
    const float* Wv = (const float*)d_in[6];
    const float* bv = (const float*)d_in[7];
    const float* Wo = (const float*)d_in[8];
    const float* bo = (const float*)d_in[9];
    float* out = (float*)d_out;

    float *q, *k, *v, *attn;
    cudaGetSymbolAddress((void**)&q,    g_q);
    cudaGetSymbolAddress((void**)&k,    g_k);
    cudaGetSymbolAddress((void**)&v,    g_v);
    cudaGetSymbolAddress((void**)&attn, g_attn);

    cudaFuncSetAttribute(qkv_gemm,  cudaFuncAttributeMaxDynamicSharedMemorySize, GEMM_SMEM);
    cudaFuncSetAttribute(oproj_gemm,cudaFuncAttributeMaxDynamicSharedMemorySize, GEMM_SMEM);
    cudaFuncSetAttribute(attn_tc,   cudaFuncAttributeMaxDynamicSharedMemorySize, ATT_SMEM);

    /* 1. convert inputs to tf32 bits */
    cvt_all<<<2048, 256>>>((const float4*)x, (const float4*)Wq,
                           (const float4*)Wk, (const float4*)Wv,
                           (const float4*)Wo);

    /* 2. fused Q/K/V projection */
    qkv_gemm<<<dim3(24, 16), 128, GEMM_SMEM>>>(bq, bk, bv);

    /* 3. causal GQA attention */
    attn_tc<<<dim3(SEQ / 128, NHEADS, BATCH), 256, ATT_SMEM>>>(q, k, v, attn);

    /* 4. output projection */
    oproj_gemm<<<dim3(16, 16), 128, GEMM_SMEM>>>(bo, out);
}

// round 7
// speedup vs baseline: 3.6812x; 1.1298x over previous
#include <cuda_runtime.h>
#include <math.h>
#include <stdint.h>

#define HIDDEN 2048
#define SEQ    1024
#define BATCH  2
#define NHEADS 32
#define NGROUP 8
#define HDIM   64
#define MTOT   (BATCH * SEQ)
#define KVW    (NGROUP * HDIM)   /* 512 */

/* ---------------- scratch (no cudaMalloc allowed) ---------------- */
__device__ float g_xt [MTOT * HIDDEN];               /* tf32 bits of x */
__device__ float g_wt [(HIDDEN + 2 * KVW) * HIDDEN]; /* Wq|Wk|Wv tf32  */
__device__ float g_wot[HIDDEN * HIDDEN];             /* Wo tf32        */
__device__ float g_q  [MTOT * HIDDEN];
__device__ float g_k  [MTOT * KVW];
__device__ float g_v  [MTOT * KVW];
__device__ float g_attn[MTOT * HIDDEN];              /* tf32 bits      */

/* ---------------- helpers ---------------- */
__device__ __forceinline__ uint32_t f2tf32(float x) {
    uint32_t r;
    asm("cvt.rna.tf32.f32 %0, %1;" : "=r"(r) : "f"(x));
    return r;
}
__device__ __forceinline__ uint32_t smem_u32(const void* p) {
    uint32_t a;
    asm("{ .reg .u64 t; cvta.to.shared.u64 t, %1; cvt.u32.u64 %0, t; }"
        : "=r"(a) : "l"(p));
    return a;
}
__device__ __forceinline__ void mma_tf32(float* c, const uint32_t* a,
                                         uint32_t b0, uint32_t b1) {
    asm volatile(
        "mma.sync.aligned.m16n8k8.row.col.f32.tf32.tf32.f32 "
        "{%0,%1,%2,%3}, {%4,%5,%6,%7}, {%8,%9}, {%0,%1,%2,%3};"
        : "+f"(c[0]), "+f"(c[1]), "+f"(c[2]), "+f"(c[3])
        : "r"(a[0]), "r"(a[1]), "r"(a[2]), "r"(a[3]), "r"(b0), "r"(b1));
}
__device__ __forceinline__ void ldsm_x4(uint32_t* r, uint32_t addr) {
    asm volatile("ldmatrix.sync.aligned.m8n8.x4.shared.b16 {%0,%1,%2,%3}, [%4];"
        : "=r"(r[0]), "=r"(r[1]), "=r"(r[2]), "=r"(r[3]) : "r"(addr));
}
__device__ __forceinline__ void cp16(uint32_t dst, const void* src) {
    asm volatile("cp.async.cg.shared.global [%0], [%1], 16;"
                 :: "r"(dst), "l"(src));
}
#define CP_COMMIT() asm volatile("cp.async.commit_group;" ::: "memory")
#define CP_WAIT0()  asm volatile("cp.async.wait_group 0;"  ::: "memory")

/* =================================================================
 * Pre-convert x, Wq|Wk|Wv, Wo to tf32 bits (grid-stride, float4).
 * ================================================================= */
__global__ void cvt_all(const float4* __restrict__ x,
                        const float4* __restrict__ wq,
                        const float4* __restrict__ wk,
                        const float4* __restrict__ wv,
                        const float4* __restrict__ wo)
{
    const int64_t N0 = 1048576;          /* x  : 4M floats  */
    const int64_t N1 = N0 + 1048576;     /* Wq : 4M         */
    const int64_t N2 = N1 + 262144;      /* Wk : 1M         */
    const int64_t N3 = N2 + 262144;      /* Wv : 1M         */
    const int64_t N4 = N3 + 1048576;     /* Wo : 4M         */
    uint4* xt  = (uint4*)g_xt;
    uint4* wt  = (uint4*)g_wt;
    uint4* wot = (uint4*)g_wot;
    for (int64_t i = (int64_t)blockIdx.x * blockDim.x + threadIdx.x;
         i < N4; i += (int64_t)gridDim.x * blockDim.x) {
        float4 v; uint4* dst;
        if (i < N0)      { v = x [i];      dst = xt  + i; }
        else if (i < N1) { v = wq[i - N0]; dst = wt  + (i - N0); }
        else if (i < N2) { v = wk[i - N1]; dst = wt  + 1048576 + (i - N1); }
        else if (i < N3) { v = wv[i - N2]; dst = wt  + 1310720 + (i - N2); }
        else             { v = wo[i - N3]; dst = wot + (i - N3); }
        uint4 u;
        u.x = f2tf32(v.x); u.y = f2tf32(v.y);
        u.z = f2tf32(v.z); u.w = f2tf32(v.w);
        *dst = u;
    }
}

/* =================================================================
 * TF32 NT GEMM, cp.async double-buffered, BK=32, swizzled 128B rows.
 * CTA 128x128, 128 threads (4 warps 2x2), warp tile 64x64.
 * 64KB smem/CTA -> 3 CTAs/SM (12 warps). Scattered cp.async.
 * Swizzle: byte chunk c (16B) of row r lives at (c ^ (r&7))*16.
 * ================================================================= */
#define BK    32
#define TILEB 16384                    /* 128 rows x 128 B          */
#define STAGE (2 * TILEB)
#define NST   2
#define GEMM_SMEM (NST * STAGE)        /* 65536                     */

__device__ __forceinline__ void gemm_core(
    const float* __restrict__ A, const float* __restrict__ Bm,
    const float* __restrict__ bias, float* __restrict__ C,
    int ldc, int K, int m0, int n0B, int n0C)
{
    extern __shared__ char smem[];
    const uint32_t sb = smem_u32(smem);
    const int tid = threadIdx.x, lane = tid & 31, wid = tid >> 5;
    const int wm = (wid & 1) * 64, wn = (wid >> 1) * 64;
    const int grp = lane >> 3;

    /* per-lane LDSM addressing: XOR mask is constant (lane&7)<<4 */
    const uint32_t xm   = (uint32_t)(lane & 7) << 4;
    const uint32_t rowA = (uint32_t)(wm + (lane & 7) + ((grp & 1) << 3)) * 128;
    const uint32_t rowB = (uint32_t)(wn + (lane & 7) + ((grp >> 1) << 3)) * 128;
    const uint32_t cA   = (uint32_t)(grp >> 1) << 4;   /* +16B for k4-7 */
    const uint32_t cB   = (uint32_t)(grp & 1) << 4;

    float acc[4][8][4];
#pragma unroll
    for (int mt = 0; mt < 4; mt++)
#pragma unroll
        for (int nt = 0; nt < 8; nt++) {
            acc[mt][nt][0] = 0.f; acc[mt][nt][1] = 0.f;
            acc[mt][nt][2] = 0.f; acc[mt][nt][3] = 0.f;
        }

    const float* Ag = A  + (size_t)(m0  + tid) * K;
    const float* Bg = Bm + (size_t)(n0B + tid) * K;
    /* cp.async destination row base + per-chunk swizzle */
    const uint32_t sRow = (uint32_t)tid * 128;
    const uint32_t sX   = (uint32_t)(tid & 7) << 4;
    const int nIter = K / BK;

    /* prologue: stage 0 */
#pragma unroll
    for (int i = 0; i < 8; i++) {
        const uint32_t d = sRow + (((uint32_t)i << 4) ^ sX);
        cp16(sb + d,         Ag + i * 4);
        cp16(sb + TILEB + d, Bg + i * 4);
    }
    CP_COMMIT();

    for (int it = 0; it < nIter; it++) {
        CP_WAIT0();
        __syncthreads();

        const uint32_t aB = sb + (it & 1) * STAGE;
        const uint32_t bB = aB + TILEB;
        const uint32_t nx = sb + ((it + 1) & 1) * STAGE;
        const bool pf = (it + 1 < nIter);
        const float* Ap = Ag + (it + 1) * BK;
        const float* Bp = Bg + (it + 1) * BK;

#pragma unroll
        for (int ks = 0; ks < 4; ks++) {
            /* scatter prefetch: 2 A + 2 B chunks per ks */
            if (pf) {
                const uint32_t d0 = sRow + ((((uint32_t)(2 * ks) << 4))     ^ sX);
                const uint32_t d1 = sRow + ((((uint32_t)(2 * ks + 1) << 4)) ^ sX);
                cp16(nx + d0,         Ap + (2 * ks) * 4);
                cp16(nx + d1,         Ap + (2 * ks + 1) * 4);
                cp16(nx + TILEB + d0, Bp + (2 * ks) * 4);
                cp16(nx + TILEB + d1, Bp + (2 * ks + 1) * 4);
            }
            const uint32_t ck = ((uint32_t)ks << 5);
            uint32_t af[4][4];
#pragma unroll
            for (int mt = 0; mt < 4; mt++)
                ldsm_x4(af[mt], aB + rowA + mt * 2048 + ((ck + cA) ^ xm));
            uint32_t bf[2][4];
            ldsm_x4(bf[0], bB + rowB + ((ck + cB) ^ xm));
#pragma unroll
            for (int nt2 = 0; nt2 < 4; nt2++) {
                const int c = nt2 & 1, n = 1 - c;
                if (nt2 < 3)
                    ldsm_x4(bf[n], bB + rowB + (nt2 + 1) * 2048 + ((ck + cB) ^ xm));
#pragma unroll
                for (int mt = 0; mt < 4; mt++) {
                    mma_tf32(acc[mt][2 * nt2],     af[mt], bf[c][0], bf[c][1]);
                    mma_tf32(acc[mt][2 * nt2 + 1], af[mt], bf[c][2], bf[c][3]);
                }
            }
        }
        CP_COMMIT();
    }

    /* epilogue: bias + float2 stores */
    const int r0 = lane >> 2, a4 = lane & 3;
#pragma unroll
    for (int mt = 0; mt < 4; mt++) {
#pragma unroll
        for (int nt = 0; nt < 8; nt++) {
            const int col = n0C + wn + nt * 8 + 2 * a4;
            const float b0 = bias[col], b1 = bias[col + 1];
            const int rA = m0 + wm + mt * 16 + r0;
            *(float2*)&C[(size_t)rA * ldc + col] =
                make_float2(acc[mt][nt][0] + b0, acc[mt][nt][1] + b1);
            *(float2*)&C[(size_t)(rA + 8) * ldc + col] =
                make_float2(acc[mt][nt][2] + b0, acc[mt][nt][3] + b1);
        }
    }
}

/* fused QKV projection: grid (24, 16) */
__global__ __launch_bounds__(128, 3) void qkv_gemm(
    const float* __restrict__ bq, const float* __restrict__ bk,
    const float* __restrict__ bv)
{
    const int n0 = blockIdx.x * 128, m0 = blockIdx.y * 128;
    const float* bias; float* C; int ldc, n0C;
    if (n0 < 2048)      { C = g_q; ldc = HIDDEN; bias = bq; n0C = n0; }
    else if (n0 < 2560) { C = g_k; ldc = KVW;    bias = bk; n0C = n0 - 2048; }
    else                { C = g_v; ldc = KVW;    bias = bv; n0C = n0 - 2560; }
    gemm_core(g_xt, g_wt, bias, C, ldc, HIDDEN, m0, n0, n0C);
}

/* O projection: grid (16, 16) */
__global__ __launch_bounds__(128, 3) void oproj_gemm(
    const float* __restrict__ bo, float* __restrict__ out)
{
    gemm_core(g_attn, g_wot, bo, out, HIDDEN, HIDDEN,
              blockIdx.y * 128, blockIdx.x * 128, blockIdx.x * 128);
}

/* =================================================================
 * Flash attention (causal, GQA): 128 q-rows per CTA, 256 threads
 * (8 warps x 16 rows), 64-col K tiles, mma.sync tf32 + ldmatrix.
 * smem: [Ks 64x68][Pext 64x68][Vt 64x68]; P = 128 rows over Ks+Pext.
 * ================================================================= */
#define ATS 68
#define ATT_SMEM (3 * 64 * ATS * 4)   /* 52224 B */

__global__ __launch_bounds__(256, 2) void attn_tc(
    const float* __restrict__ Q, const float* __restrict__ Kp,
    const float* __restrict__ Vp, float* __restrict__ Out)
{
    extern __shared__ uint32_t sm[];
    uint32_t* Ks = sm;
    uint32_t* Vt = sm + 2 * 64 * ATS;

    const int qt = (int)gridDim.x - 1 - (int)blockIdx.x;  /* longest first */
    const int h = blockIdx.y, b = blockIdx.z, g = h >> 2;
    const int tid = threadIdx.x, lane = tid & 31, w = tid >> 5;
    const int r0 = lane >> 2, a4 = lane & 3;

    const int grp = lane >> 3;
    const uint32_t paOff = (uint32_t)(w * 16 + (lane & 7) + ((grp & 1) << 3)) * 272
                         + (uint32_t)(grp >> 1) * 16;
    const uint32_t bfOff = (uint32_t)((lane & 7) + ((grp >> 1) << 3)) * 272
                         + (uint32_t)(grp & 1) * 16;
    const uint32_t ksBase = smem_u32(sm);
    const uint32_t vtBase = ksBase + 2 * 64 * ATS * 4;

    uint32_t qf[8][4];
    {
        const float sc = 0.125f;
        const float* qp = Q + (size_t)(b * SEQ + qt * 128 + w * 16) * HIDDEN + h * HDIM;
#pragma unroll
        for (int ks = 0; ks < 8; ks++) {
            const int c = ks * 8 + a4;
            qf[ks][0] = f2tf32(qp[(size_t)r0 * HIDDEN + c] * sc);
            qf[ks][1] = f2tf32(qp[(size_t)(r0 + 8) * HIDDEN + c] * sc);
            qf[ks][2] = f2tf32(qp[(size_t)r0 * HIDDEN + c + 4] * sc);
            qf[ks][3] = f2tf32(qp[(size_t)(r0 + 8) * HIDDEN + c + 4] * sc);
        }
    }

    float o[8][4];
#pragma unroll
    for (int nt = 0; nt < 8; nt++) {
        o[nt][0] = 0.f; o[nt][1] = 0.f; o[nt][2] = 0.f; o[nt][3] = 0.f;
    }
    float mi0 = -1e30f, mi1 = -1e30f, l0 = 0.f, l1 = 0.f;

    const int lrow = tid >> 2;
    const int lcb  = (tid & 3) * 16;
    const int ktEnd = 2 * qt + 1;

    for (int kt = 0; kt <= ktEnd; kt++) {
        __syncthreads();

        {
            const size_t base = (size_t)(b * SEQ + kt * 64 + lrow) * KVW + g * HDIM + lcb;
            const float* kp = Kp + base;
            const float* vp = Vp + base;
#pragma unroll
            for (int u = 0; u < 4; u++) {
                float4 kv = *(const float4*)(kp + u * 4);
                uint32_t* kd = &Ks[lrow * ATS + lcb + u * 4];
                kd[0] = f2tf32(kv.x); kd[1] = f2tf32(kv.y);
                kd[2] = f2tf32(kv.z); kd[3] = f2tf32(kv.w);
                float4 vv = *(const float4*)(vp + u * 4);
                const int c = lcb + u * 4;
                Vt[(c + 0) * ATS + lrow] = f2tf32(vv.x);
                Vt[(c + 1) * ATS + lrow] = f2tf32(vv.y);
                Vt[(c + 2) * ATS + lrow] = f2tf32(vv.z);
                Vt[(c + 3) * ATS + lrow] = f2tf32(vv.w);
            }
        }
        __syncthreads();

        float s[8][4];
#pragma unroll
        for (int nt = 0; nt < 8; nt++) {
            s[nt][0] = 0.f; s[nt][1] = 0.f; s[nt][2] = 0.f; s[nt][3] = 0.f;
        }
#pragma unroll
        for (int ks = 0; ks < 8; ks++) {
#pragma unroll
            for (int nt2 = 0; nt2 < 4; nt2++) {
                uint32_t bf[4];
                ldsm_x4(bf, ksBase + bfOff + nt2 * 4352 + ks * 32);
                mma_tf32(s[2 * nt2],     qf[ks], bf[0], bf[1]);
                mma_tf32(s[2 * nt2 + 1], qf[ks], bf[2], bf[3]);
            }
        }

        if (kt >= 2 * qt) {
            const int diff  = (kt - 2 * qt) * 64;
            const int row0g = w * 16 + r0, row1g = row0g + 8;
#pragma unroll
            for (int nt = 0; nt < 8; nt++) {
                const int c0 = nt * 8 + 2 * a4 + diff, c1 = c0 + 1;
                if (c0 > row0g) s[nt][0] = -1e30f;
                if (c1 > row0g) s[nt][1] = -1e30f;
                if (c0 > row1g) s[nt][2] = -1e30f;
                if (c1 > row1g) s[nt][3] = -1e30f;
            }
        }

        float mx0 = -1e30f, mx1 = -1e30f;
#pragma unroll
        for (int nt = 0; nt < 8; nt++) {
            mx0 = fmaxf(mx0, fmaxf(s[nt][0], s[nt][1]));
            mx1 = fmaxf(mx1, fmaxf(s[nt][2], s[nt][3]));
        }
        mx0 = fmaxf(mx0, __shfl_xor_sync(0xffffffffu, mx0, 1));
        mx0 = fmaxf(mx0, __shfl_xor_sync(0xffffffffu, mx0, 2));
        mx1 = fmaxf(mx1, __shfl_xor_sync(0xffffffffu, mx1, 1));
        mx1 = fmaxf(mx1, __shfl_xor_sync(0xffffffffu, mx1, 2));
        const float nm0 = fmaxf(mi0, mx0), nm1 = fmaxf(mi1, mx1);
        const float cr0 = __expf(mi0 - nm0), cr1 = __expf(mi1 - nm1);
        float sum0 = 0.f, sum1 = 0.f;
#pragma unroll
        for (int nt = 0; nt < 8; nt++) {
            s[nt][0] = __expf(s[nt][0] - nm0);
            s[nt][1] = __expf(s[nt][1] - nm0);
            s[nt][2] = __expf(s[nt][2] - nm1);
            s[nt][3] = __expf(s[nt][3] - nm1);
            sum0 += s[nt][0] + s[nt][1];
            sum1 += s[nt][2] + s[nt][3];
        }
        sum0 += __shfl_xor_sync(0xffffffffu, sum0, 1);
        sum0 += __shfl_xor_sync(0xffffffffu, sum0, 2);
        sum1 += __shfl_xor_sync(0xffffffffu, sum1, 1);
        sum1 += __shfl_xor_sync(0xffffffffu, sum1, 2);
        l0 = l0 * cr0 + sum0;  l1 = l1 * cr1 + sum1;
        mi0 = nm0;             mi1 = nm1;
#pragma unroll
        for (int nt = 0; nt < 8; nt++) {
            o[nt][0] *= cr0; o[nt][1] *= cr0;
            o[nt][2] *= cr1; o[nt][3] *= cr1;
        }

        __syncthreads();

        {
            const int row0 = w * 16 + r0;
#pragma unroll
            for (int nt = 0; nt < 8; nt++) {
                const int c = nt * 8 + 2 * a4;
                sm[row0 * ATS + c]           = f2tf32(s[nt][0]);
                sm[row0 * ATS + c + 1]       = f2tf32(s[nt][1]);
                sm[(row0 + 8) * ATS + c]     = f2tf32(s[nt][2]);
                sm[(row0 + 8) * ATS + c + 1] = f2tf32(s[nt][3]);
            }
        }
        __syncwarp();

#pragma unroll
        for (int ks = 0; ks < 8; ks++) {
            uint32_t pa[4];
            ldsm_x4(pa, ksBase + paOff + ks * 32);
#pragma unroll
            for (int nt2 = 0; nt2 < 4; nt2++) {
                uint32_t bf[4];
                ldsm_x4(bf, vtBase + bfOff + nt2 * 4352 + ks * 32);
                mma_tf32(o[2 * nt2],     pa, bf[0], bf[1]);
                mma_tf32(o[2 * nt2 + 1], pa, bf[2], bf[3]);
            }
        }
    }

    const float inv0 = 1.f / l0, inv1 = 1.f / l1;
    const size_t row0 = (size_t)(b * SEQ + qt * 128 + w * 16 + r0);
#pragma unroll
    for (int nt = 0; nt < 8; nt++) {
        const int col = h * HDIM + nt * 8 + 2 * a4;
        *(float2*)&Out[row0 * HIDDEN + col] = make_float2(
            __uint_as_float(f2tf32(o[nt][0] * inv0)),
            __uint_as_float(f2tf32(o[nt][1] * inv0)));
        *(float2*)&Out[(row0 + 8) * HIDDEN + col] = make_float2(
            __uint_as_float(f2tf32(o[nt][2] * inv1)),
            __uint_as_float(f2tf32(o[nt][3] * inv1)));
    }
}

/* ================================================================= */
extern "C" void kernel_launch(void* const* d_in, const int* in_sizes, int n_in,
                              void* d_out, int out_size)
{
    (void)in_sizes; (void)n_in; (void)out_size;
    const float* x  = (const float*)d_in[0];
    /* d_in[1] = causal mask, handled analytically */
    const float* Wq = (const float*)d_in[2];
    const float* bq = (const float*)d_in[3];
    const float* Wk = (const float*)d_in[4];
    const float* bk = (const float*)d_in[5];
    const float* Wv = (const float*)d_in[6];
    const float* bv = (const float*)d_in[7];
    const float* Wo = (const float*)d_in[8];
    const float* bo = (const float*)d_in[9];
    float* out = (float*)d_out;

    float *q, *k, *v, *attn;
    cudaGetSymbolAddress((void**)&q,    g_q);
    cudaGetSymbolAddress((void**)&k,    g_k);
    cudaGetSymbolAddress((void**)&v,    g_v);
    cudaGetSymbolAddress((void**)&attn, g_attn);

    cudaFuncSetAttribute(qkv_gemm,   cudaFuncAttributeMaxDynamicSharedMemorySize, GEMM_SMEM);
    cudaFuncSetAttribute(oproj_gemm, cudaFuncAttributeMaxDynamicSharedMemorySize, GEMM_SMEM);
    cudaFuncSetAttribute(attn_tc,    cudaFuncAttributeMaxDynamicSharedMemorySize, ATT_SMEM);

    /* 1. convert inputs to tf32 bits */
    cvt_all<<<2048, 256>>>((const float4*)x, (const float4*)Wq,
                           (const float4*)Wk, (const float4*)Wv,
                           (const float4*)Wo);

    /* 2. fused Q/K/V projection */
    qkv_gemm<<<dim3(24, 16), 128, GEMM_SMEM>>>(bq, bk, bv);

    /* 3. causal GQA attention */
    attn_tc<<<dim3(SEQ / 128, NHEADS, BATCH), 256, ATT_SMEM>>>(q, k, v, attn);

    /* 4. output projection */
    oproj_gemm<<<dim3(16, 16), 128, GEMM_SMEM>>>(bo, out);
}